// round 1
// baseline (speedup 1.0000x reference)
#include <cuda_runtime.h>

// ---------------- Problem constants ----------------
#define NA   20001      // atoms (incl padding atom 0)
#define FD   133        // atom feature dim
#define KNB  6          // max neighbors
#define HD   1100       // hidden dim
#define FHD  700        // ffn hidden dim
#define NM   800        // molecules
#define F2   266        // 2*FD
#define OSK  1233       // FD + HD
#define OVK  2200       // 2*HD
#define FFK  1400       // 2*FHD

// ---------------- Scratch (device globals: allocation-free) ----------------
__device__ float g_si  [(size_t)NA * HD];
__device__ float g_s   [(size_t)NA * HD];
__device__ float g_sagg[(size_t)NA * HD];
__device__ float g_vi  [(size_t)NA * 3 * HD];
__device__ float g_v   [(size_t)NA * 3 * HD];
__device__ float g_vagg[(size_t)NA * 3 * HD];
__device__ float g_X   [(size_t)NA * 3 * F2];
__device__ float g_osin[(size_t)NA * OSK];
__device__ float g_ovin[(size_t)NA * 3 * OVK];
__device__ float g_osb [(size_t)NA * FHD];
__device__ float g_ovb [(size_t)NA * 3 * FHD];
__device__ float g_o   [(size_t)NA * FFK];
__device__ float g_mol [NM * FFK];
__device__ float g_h   [NM * FHD];
__device__ float g_invn[NA];
__device__ int   g_molstart[NM + 1];

// ---------------- Generic SGEMM: C = act(A@B [+ Add] [+ bias]) ----------------
#define BM 128
#define BN 128
#define BKK 8
#define TM 8
#define TN 8

template<bool RELU, bool HAS_ADD, bool HAS_BIAS, bool WRITE_RAW>
__global__ __launch_bounds__(256, 2)
void sgemm_kernel(const float* __restrict__ A, const float* __restrict__ B,
                  const float* __restrict__ Add, const float* __restrict__ bias,
                  float* __restrict__ C, float* __restrict__ Craw,
                  int M, int N, int Kd)
{
    __shared__ float As[BKK][BM + 4];   // +4 pad: conflict-free STS
    __shared__ float Bs[BKK][BN];

    const int tid = threadIdx.x;
    const int tx  = tid & 15;
    const int ty  = tid >> 4;
    const int rowBase = blockIdx.y * BM;
    const int colBase = blockIdx.x * BN;

    float acc[TM][TN];
    #pragma unroll
    for (int i = 0; i < TM; i++)
        #pragma unroll
        for (int j = 0; j < TN; j++) acc[i][j] = 0.f;

    for (int k0 = 0; k0 < Kd; k0 += BKK) {
        // A tile: 128x8, transposed into As[k][m]
        #pragma unroll
        for (int i = 0; i < 4; i++) {
            int e = tid + i * 256;
            int m = e >> 3, k = e & 7;
            int gm = rowBase + m, gk = k0 + k;
            float val = 0.f;
            if (gm < M && gk < Kd) val = A[(size_t)gm * Kd + gk];
            As[k][m] = val;
        }
        // B tile: 8x128
        #pragma unroll
        for (int i = 0; i < 4; i++) {
            int e = tid + i * 256;
            int k = e >> 7, n = e & 127;
            int gk = k0 + k, gn = colBase + n;
            float val = 0.f;
            if (gk < Kd && gn < N) val = B[(size_t)gk * N + gn];
            Bs[k][n] = val;
        }
        __syncthreads();

        #pragma unroll
        for (int k = 0; k < BKK; k++) {
            float a[TM], b[TN];
            #pragma unroll
            for (int i = 0; i < TM; i++) a[i] = As[k][ty * TM + i];
            #pragma unroll
            for (int j = 0; j < TN; j++) b[j] = Bs[k][tx * TN + j];
            #pragma unroll
            for (int i = 0; i < TM; i++)
                #pragma unroll
                for (int j = 0; j < TN; j++) acc[i][j] += a[i] * b[j];
        }
        __syncthreads();
    }

    #pragma unroll
    for (int i = 0; i < TM; i++) {
        int gm = rowBase + ty * TM + i;
        if (gm >= M) continue;
        #pragma unroll
        for (int j = 0; j < TN; j++) {
            int gn = colBase + tx * TN + j;
            if (gn >= N) continue;
            size_t idx = (size_t)gm * N + gn;
            float v = acc[i][j];
            if (HAS_ADD)  v += Add[idx];
            if (HAS_BIAS) v += bias[gn];
            if (WRITE_RAW) Craw[idx] = v;
            C[idx] = RELU ? fmaxf(v, 0.f) : v;
        }
    }
}

// ---------------- invnorm: 1/max(#neighbors,1) ----------------
__global__ void invnorm_kernel(const int* __restrict__ a2a, float* __restrict__ invn)
{
    int n = blockIdx.x * blockDim.x + threadIdx.x;
    if (n >= NA) return;
    int cnt = 0;
    #pragma unroll
    for (int k = 0; k < KNB; k++) cnt += (a2a[n * KNB + k] > 0) ? 1 : 0;
    invn[n] = 1.f / (float)max(cnt, 1);
}

// ---------------- X[n,c,f2] = einsum('nkf,nkc->ncf', [s_nei|self*mask], bond) ----------------
__global__ void build_X_kernel(const float* __restrict__ f_atoms, const float* __restrict__ f_bonds,
                               const int* __restrict__ a2a, const int* __restrict__ a2b,
                               float* __restrict__ X)
{
    int n = blockIdx.x;
    __shared__ int   nb[KNB];
    __shared__ float bond[KNB][3];
    if (threadIdx.x < KNB) {
        int k = threadIdx.x;
        nb[k] = a2a[n * KNB + k];
        int b = a2b[n * KNB + k];
        bond[k][0] = f_bonds[(size_t)b * 3 + 0];
        bond[k][1] = f_bonds[(size_t)b * 3 + 1];
        bond[k][2] = f_bonds[(size_t)b * 3 + 2];
    }
    __syncthreads();
    float ms0 = 0.f, ms1 = 0.f, ms2 = 0.f;
    #pragma unroll
    for (int k = 0; k < KNB; k++) {
        float mk = (nb[k] > 0) ? 1.f : 0.f;
        ms0 += mk * bond[k][0];
        ms1 += mk * bond[k][1];
        ms2 += mk * bond[k][2];
    }
    for (int f = threadIdx.x; f < FD; f += blockDim.x) {
        float selfv = f_atoms[(size_t)n * FD + f];
        float a0 = 0.f, a1 = 0.f, a2 = 0.f;
        #pragma unroll
        for (int k = 0; k < KNB; k++) {
            float fv = f_atoms[(size_t)nb[k] * FD + f];
            a0 += fv * bond[k][0];
            a1 += fv * bond[k][1];
            a2 += fv * bond[k][2];
        }
        size_t base = (size_t)n * 3 * F2;
        X[base + 0 * F2 + f] = a0;
        X[base + 1 * F2 + f] = a1;
        X[base + 2 * F2 + f] = a2;
        X[base + 0 * F2 + FD + f] = selfv * ms0;
        X[base + 1 * F2 + FD + f] = selfv * ms1;
        X[base + 2 * F2 + FD + f] = selfv * ms2;
    }
}

// ---------------- neighbor gather-sum: sagg = sum_k s[nb]; vagg = sum_k v[nb] [* invnorm] ----------------
template<bool DIVV>
__global__ void gather_kernel(const float* __restrict__ s, const float* __restrict__ v,
                              const int* __restrict__ a2a, const float* __restrict__ invn,
                              float* __restrict__ sagg, float* __restrict__ vagg)
{
    int n = blockIdx.x;
    __shared__ int nb[KNB];
    __shared__ float invsh;
    if (threadIdx.x < KNB) nb[threadIdx.x] = a2a[n * KNB + threadIdx.x];
    if (threadIdx.x == KNB) invsh = invn[n];
    __syncthreads();
    size_t b0 = (size_t)nb[0] * HD, b1 = (size_t)nb[1] * HD, b2 = (size_t)nb[2] * HD;
    size_t b3 = (size_t)nb[3] * HD, b4 = (size_t)nb[4] * HD, b5 = (size_t)nb[5] * HD;
    for (int h = threadIdx.x; h < HD; h += blockDim.x) {
        float acc = s[b0 + h] + s[b1 + h] + s[b2 + h] + s[b3 + h] + s[b4 + h] + s[b5 + h];
        sagg[(size_t)n * HD + h] = acc;
    }
    float sc = DIVV ? invsh : 1.f;
    size_t c0 = b0 * 3, c1 = b1 * 3, c2 = b2 * 3, c3 = b3 * 3, c4 = b4 * 3, c5 = b5 * 3;
    for (int e = threadIdx.x; e < 3 * HD; e += blockDim.x) {
        float acc = v[c0 + e] + v[c1 + e] + v[c2 + e] + v[c3 + e] + v[c4 + e] + v[c5 + e];
        vagg[(size_t)n * 3 * HD + e] = acc * sc;
    }
}

// ---------------- concat builders ----------------
__global__ void build_osin_kernel(const float* __restrict__ fa, const float* __restrict__ sagg,
                                  float* __restrict__ osin)
{
    for (long idx = (long)blockIdx.x * blockDim.x + threadIdx.x; idx < (long)NA * OSK;
         idx += (long)gridDim.x * blockDim.x) {
        int n = (int)(idx / OSK);
        int j = (int)(idx % OSK);
        osin[idx] = (j < FD) ? fa[(size_t)n * FD + j] : sagg[(size_t)n * HD + (j - FD)];
    }
}

__global__ void build_ovin_kernel(const float* __restrict__ vi, const float* __restrict__ vagg,
                                  float* __restrict__ ovin)
{
    for (long idx = (long)blockIdx.x * blockDim.x + threadIdx.x; idx < (long)NA * 3 * OVK;
         idx += (long)gridDim.x * blockDim.x) {
        long r = idx / OVK;          // row in [0, 3*NA): (n*3+c)
        int  j = (int)(idx % OVK);
        ovin[idx] = (j < HD) ? vi[r * HD + j] : vagg[r * HD + (j - HD)];
    }
}

// o[n] = [os_[n] | sum_c ov[n,c,:]]
__global__ void build_o_kernel(const float* __restrict__ osb, const float* __restrict__ ovb,
                               float* __restrict__ o)
{
    for (long idx = (long)blockIdx.x * blockDim.x + threadIdx.x; idx < (long)NA * FFK;
         idx += (long)gridDim.x * blockDim.x) {
        int n = (int)(idx / FFK);
        int j = (int)(idx % FFK);
        if (j < FHD) {
            o[idx] = osb[(size_t)n * FHD + j];
        } else {
            int jj = j - FHD;
            size_t b = (size_t)n * 3 * FHD + jj;
            o[idx] = ovb[b] + ovb[b + FHD] + ovb[b + 2 * FHD];
        }
    }
}

// ---------------- readout ----------------
__global__ void mol_start_kernel(const int* __restrict__ ids, int* __restrict__ start)
{
    int m = blockIdx.x * blockDim.x + threadIdx.x;
    if (m > NM) return;
    int lo = 0, hi = NA;
    while (lo < hi) {
        int mid = (lo + hi) >> 1;
        if (ids[mid] < m) lo = mid + 1; else hi = mid;
    }
    start[m] = lo;
}

__global__ void segment_mean_kernel(const float* __restrict__ o, const int* __restrict__ start,
                                    float* __restrict__ mol)
{
    int m = blockIdx.x;
    int s0 = start[m], e0 = start[m + 1];
    int cnt = e0 - s0;
    if (s0 == 0 && e0 > 0) cnt -= 1;   // atom 0 is padding
    float sc = 1.f / (float)max(cnt, 1);
    for (int f = threadIdx.x; f < FFK; f += blockDim.x) {
        float acc = 0.f;
        for (int n = s0; n < e0; n++) {
            if (n == 0) continue;
            acc += o[(size_t)n * FFK + f];
        }
        mol[m * FFK + f] = acc * sc;
    }
}

__global__ void ffn_out_kernel(const float* __restrict__ h, const float* __restrict__ W2,
                               const float* __restrict__ b2, float* __restrict__ out)
{
    int m = blockIdx.x;
    float acc = 0.f;
    for (int j = threadIdx.x; j < FHD; j += 256) acc += h[m * FHD + j] * W2[j];
    __shared__ float red[256];
    red[threadIdx.x] = acc;
    __syncthreads();
    for (int st = 128; st > 0; st >>= 1) {
        if (threadIdx.x < st) red[threadIdx.x] += red[threadIdx.x + st];
        __syncthreads();
    }
    if (threadIdx.x == 0) out[m] = red[0] + b2[0];
}

// ---------------- launch ----------------
extern "C" void kernel_launch(void* const* d_in, const int* in_sizes, int n_in,
                              void* d_out, int out_size)
{
    const float* f_atoms = (const float*)d_in[0];
    const float* f_bonds = (const float*)d_in[1];
    const float* W_is    = (const float*)d_in[2];
    const float* W_iv    = (const float*)d_in[3];
    const float* W_hs    = (const float*)d_in[4];
    const float* W_hv    = (const float*)d_in[5];
    const float* W_os    = (const float*)d_in[6];
    const float* b_os    = (const float*)d_in[7];
    const float* W_ov    = (const float*)d_in[8];
    const float* b_ov    = (const float*)d_in[9];
    const float* ffn_W1  = (const float*)d_in[10];
    const float* ffn_b1  = (const float*)d_in[11];
    const float* ffn_W2  = (const float*)d_in[12];
    const float* ffn_b2  = (const float*)d_in[13];
    const int*   a2a     = (const int*)d_in[14];
    const int*   a2b     = (const int*)d_in[15];
    const int*   mol_ids = (const int*)d_in[16];
    float*       out     = (float*)d_out;

    float *p_si, *p_s, *p_sagg, *p_vi, *p_v, *p_vagg, *p_X, *p_osin, *p_ovin;
    float *p_osb, *p_ovb, *p_o, *p_mol, *p_h, *p_invn;
    int* p_molstart;
    cudaGetSymbolAddress((void**)&p_si,   g_si);
    cudaGetSymbolAddress((void**)&p_s,    g_s);
    cudaGetSymbolAddress((void**)&p_sagg, g_sagg);
    cudaGetSymbolAddress((void**)&p_vi,   g_vi);
    cudaGetSymbolAddress((void**)&p_v,    g_v);
    cudaGetSymbolAddress((void**)&p_vagg, g_vagg);
    cudaGetSymbolAddress((void**)&p_X,    g_X);
    cudaGetSymbolAddress((void**)&p_osin, g_osin);
    cudaGetSymbolAddress((void**)&p_ovin, g_ovin);
    cudaGetSymbolAddress((void**)&p_osb,  g_osb);
    cudaGetSymbolAddress((void**)&p_ovb,  g_ovb);
    cudaGetSymbolAddress((void**)&p_o,    g_o);
    cudaGetSymbolAddress((void**)&p_mol,  g_mol);
    cudaGetSymbolAddress((void**)&p_h,    g_h);
    cudaGetSymbolAddress((void**)&p_invn, g_invn);
    cudaGetSymbolAddress((void**)&p_molstart, g_molstart);

    // 1. norm + input-stage einsum
    invnorm_kernel<<<(NA + 255) / 256, 256>>>(a2a, p_invn);
    build_X_kernel<<<NA, 128>>>(f_atoms, f_bonds, a2a, a2b, p_X);

    // 2. si = f_atoms @ W_is (raw -> g_si, relu -> g_s)
    dim3 gsi((HD + BN - 1) / BN, (NA + BM - 1) / BM);
    sgemm_kernel<true, false, false, true><<<gsi, 256>>>(
        f_atoms, W_is, nullptr, nullptr, p_s, p_si, NA, HD, FD);

    // 3. vi = X @ W_iv (raw -> g_vi, relu -> g_v), M = 3*NA
    dim3 gvi((HD + BN - 1) / BN, (3 * NA + BM - 1) / BM);
    sgemm_kernel<true, false, false, true><<<gvi, 256>>>(
        p_X, W_iv, nullptr, nullptr, p_v, p_vi, 3 * NA, HD, F2);

    // 4. message passing, 6 iterations
    for (int it = 0; it < 6; it++) {
        gather_kernel<true><<<NA, 256>>>(p_s, p_v, a2a, p_invn, p_sagg, p_vagg);
        sgemm_kernel<true, true, false, false><<<gsi, 256>>>(
            p_sagg, W_hs, p_si, nullptr, p_s, nullptr, NA, HD, HD);
        sgemm_kernel<true, true, false, false><<<gvi, 256>>>(
            p_vagg, W_hv, p_vi, nullptr, p_v, nullptr, 3 * NA, HD, HD);
    }

    // 5. output stage
    gather_kernel<false><<<NA, 256>>>(p_s, p_v, a2a, p_invn, p_sagg, p_vagg);
    {
        long tot1 = (long)NA * OSK;
        build_osin_kernel<<<(unsigned)((tot1 + 255) / 256), 256>>>(f_atoms, p_sagg, p_osin);
        long tot2 = (long)NA * 3 * OVK;
        build_ovin_kernel<<<(unsigned)((tot2 + 255) / 256), 256>>>(p_vi, p_vagg, p_ovin);
    }
    dim3 gos((FHD + BN - 1) / BN, (NA + BM - 1) / BM);
    sgemm_kernel<true, false, true, false><<<gos, 256>>>(
        p_osin, W_os, nullptr, b_os, p_osb, nullptr, NA, FHD, OSK);
    dim3 gov((FHD + BN - 1) / BN, (3 * NA + BM - 1) / BM);
    sgemm_kernel<true, false, true, false><<<gov, 256>>>(
        p_ovin, W_ov, nullptr, b_ov, p_ovb, nullptr, 3 * NA, FHD, OVK);
    {
        long tot3 = (long)NA * FFK;
        build_o_kernel<<<(unsigned)((tot3 + 255) / 256), 256>>>(p_osb, p_ovb, p_o);
    }

    // 6. readout + FFN
    mol_start_kernel<<<4, 256>>>(mol_ids, p_molstart);
    segment_mean_kernel<<<NM, 256>>>(p_o, p_molstart, p_mol);
    dim3 gff((FHD + BN - 1) / BN, (NM + BM - 1) / BM);
    sgemm_kernel<true, false, true, false><<<gff, 256>>>(
        p_mol, ffn_W1, nullptr, ffn_b1, p_h, nullptr, NM, FHD, FFK);
    ffn_out_kernel<<<NM, 256>>>(p_h, ffn_W2, ffn_b2, out);
}

// round 4
// speedup vs baseline: 1.2728x; 1.2728x over previous
#include <cuda_runtime.h>

// ---------------- Problem constants ----------------
#define NA   20001      // atoms (incl padding atom 0)
#define FD   133        // atom feature dim
#define KNB  6          // max neighbors
#define HD   1100       // hidden dim
#define FHD  700        // ffn hidden dim
#define NM   800        // molecules
#define F2   266        // 2*FD
#define OSK  1233       // FD + HD
#define OVK  2200       // 2*HD
#define FFK  1400       // 2*FHD

// padded A-side strides (16B-aligned rows for cp.async)
#define FDP  136        // f_atoms padded
#define F2P  272        // X padded
#define OSKP 1236       // osin padded

// ---------------- Scratch (device globals: allocation-free) ----------------
__device__ __align__(16) float g_fapad[(size_t)NA * FDP];
__device__ __align__(16) float g_si  [(size_t)NA * HD];
__device__ __align__(16) float g_s   [(size_t)NA * HD];
__device__ __align__(16) float g_sagg[(size_t)NA * HD];
__device__ __align__(16) float g_vi  [(size_t)NA * 3 * HD];
__device__ __align__(16) float g_v   [(size_t)NA * 3 * HD];
__device__ __align__(16) float g_vagg[(size_t)NA * 3 * HD];
__device__ __align__(16) float g_X   [(size_t)NA * 3 * F2P];
__device__ __align__(16) float g_osin[(size_t)NA * OSKP];
__device__ __align__(16) float g_ovin[(size_t)NA * 3 * OVK];
__device__ __align__(16) float g_osb [(size_t)NA * FHD];
__device__ __align__(16) float g_ovb [(size_t)NA * 3 * FHD];
__device__ __align__(16) float g_o   [(size_t)NA * FFK];
__device__ __align__(16) float g_mol [NM * FFK];
__device__ __align__(16) float g_h   [NM * FHD];
__device__ __align__(16) float g_invn[NA];
__device__ int   g_molstart[NM + 1];

// ---------------- TF32x3 tensor-core GEMM (fp32-accurate) ----------------
// C[M,N] = act(A[M,Kd] @ B[Kd,N] [+ Add] [+ bias])
// Each fp32 operand is split x = hi + lo (hi = tf32(x), lo = tf32(x - hi)).
// acc += a_hi*b_hi + a_hi*b_lo + a_lo*b_hi  -> ~1e-7 relative error.

#define BM 128
#define BN 128
#define BK 16
#define AST 20    // A smem row stride (floats): conflict-free fragment reads
#define BST 136   // B smem row stride (floats)

__device__ __forceinline__ void tf32split(float x, unsigned& hi, unsigned& lo) {
    unsigned h;
    asm("cvt.rna.tf32.f32 %0, %1;\n" : "=r"(h) : "f"(x));
    float hf = __uint_as_float(h);     // tf32 pattern is a valid fp32 (13 low bits 0)
    float lf = x - hf;                 // exactly representable
    unsigned l;
    asm("cvt.rna.tf32.f32 %0, %1;\n" : "=r"(l) : "f"(lf));
    hi = h; lo = l;
}

__device__ __forceinline__ void cp16(float* dst_smem, const float* src, int bytes) {
    unsigned sa = (unsigned)__cvta_generic_to_shared(dst_smem);
    asm volatile("cp.async.ca.shared.global [%0], [%1], 16, %2;\n"
                 :: "r"(sa), "l"(src), "r"(bytes));
}

#define MMA_TF32(ACC, AF, BF)                                                   \
    asm volatile(                                                               \
        "mma.sync.aligned.m16n8k8.row.col.f32.tf32.tf32.f32 "                   \
        "{%0,%1,%2,%3}, {%4,%5,%6,%7}, {%8,%9}, {%0,%1,%2,%3};\n"               \
        : "+f"(ACC[0]), "+f"(ACC[1]), "+f"(ACC[2]), "+f"(ACC[3])                \
        : "r"(AF[0]), "r"(AF[1]), "r"(AF[2]), "r"(AF[3]),                       \
          "r"(BF[0]), "r"(BF[1]))

template<bool RELU, bool HAS_ADD, bool HAS_BIAS, bool WRITE_RAW>
__global__ __launch_bounds__(256)
void tgemm_kernel(const float* __restrict__ A, const float* __restrict__ B,
                  const float* __restrict__ Add, const float* __restrict__ bias,
                  float* __restrict__ C, float* __restrict__ Craw,
                  int M, int N, int Kd, int lda, int KA)
{
    __shared__ float As[2][BM][AST];
    __shared__ float Bs[2][BK][BST];

    const int tid = threadIdx.x;
    const int rowBase = blockIdx.y * BM;
    const int colBase = blockIdx.x * BN;
    const int warpId = tid >> 5;
    const int lane = tid & 31;
    const int g  = lane >> 2;        // group id (0..7)
    const int tg = lane & 3;         // thread-in-group (0..3)
    const int wm = (warpId & 1) * 64;
    const int wn = (warpId >> 1) * 32;

    float acc[4][4][4];
    #pragma unroll
    for (int mi = 0; mi < 4; mi++)
        #pragma unroll
        for (int ni = 0; ni < 4; ni++)
            #pragma unroll
            for (int j = 0; j < 4; j++) acc[mi][ni][j] = 0.f;

    const int T = (Kd + BK - 1) / BK;

    auto load_tile = [&](int t, int st) {
        const int kt = t * BK;
        #pragma unroll
        for (int i = 0; i < 2; i++) {
            int c = tid + i * 256;
            int m = c >> 2, kq = (c & 3) << 2;
            int gm = rowBase + m, gk = kt + kq;
            bool ok = (gm < M) && (gk < KA);
            const float* src = ok ? (A + (size_t)gm * lda + gk) : A;
            cp16(&As[st][m][kq], src, ok ? 16 : 0);
        }
        #pragma unroll
        for (int i = 0; i < 2; i++) {
            int c = tid + i * 256;
            int k = c >> 5, n = (c & 31) << 2;
            int gk = kt + k, gn = colBase + n;
            bool ok = (gk < Kd) && (gn < N);
            const float* src = ok ? (B + (size_t)gk * N + gn) : B;
            cp16(&Bs[st][k][n], src, ok ? 16 : 0);
        }
        asm volatile("cp.async.commit_group;\n");
    };

    load_tile(0, 0);
    int st = 0;

    for (int t = 0; t < T; t++) {
        if (t + 1 < T) {
            load_tile(t + 1, st ^ 1);
            asm volatile("cp.async.wait_group 1;\n");
        } else {
            asm volatile("cp.async.wait_group 0;\n");
        }
        __syncthreads();

        #pragma unroll
        for (int ks = 0; ks < 2; ks++) {
            const int k0 = ks * 8;
            unsigned ah[4][4], al[4][4], bh[4][2], bl[4][2];
            #pragma unroll
            for (int mi = 0; mi < 4; mi++) {
                int m = wm + mi * 16 + g;
                tf32split(As[st][m    ][k0 + tg    ], ah[mi][0], al[mi][0]);
                tf32split(As[st][m + 8][k0 + tg    ], ah[mi][1], al[mi][1]);
                tf32split(As[st][m    ][k0 + tg + 4], ah[mi][2], al[mi][2]);
                tf32split(As[st][m + 8][k0 + tg + 4], ah[mi][3], al[mi][3]);
            }
            #pragma unroll
            for (int ni = 0; ni < 4; ni++) {
                int n = wn + ni * 8 + g;
                tf32split(Bs[st][k0 + tg    ][n], bh[ni][0], bl[ni][0]);
                tf32split(Bs[st][k0 + tg + 4][n], bh[ni][1], bl[ni][1]);
            }
            #pragma unroll
            for (int mi = 0; mi < 4; mi++)
                #pragma unroll
                for (int ni = 0; ni < 4; ni++) {
                    MMA_TF32(acc[mi][ni], ah[mi], bl[ni]);   // hi*lo
                    MMA_TF32(acc[mi][ni], al[mi], bh[ni]);   // lo*hi
                    MMA_TF32(acc[mi][ni], ah[mi], bh[ni]);   // hi*hi (last: largest term)
                }
        }
        __syncthreads();
        st ^= 1;
    }

    // ---- epilogue ----
    #pragma unroll
    for (int mi = 0; mi < 4; mi++) {
        int r0 = rowBase + wm + mi * 16 + g;
        #pragma unroll
        for (int ni = 0; ni < 4; ni++) {
            int cN = colBase + wn + ni * 8 + tg * 2;
            if (cN >= N) continue;
            #pragma unroll
            for (int half = 0; half < 2; half++) {
                int r = r0 + half * 8;
                if (r >= M) continue;
                size_t idx = (size_t)r * N + cN;
                float v0 = acc[mi][ni][half * 2 + 0];
                float v1 = acc[mi][ni][half * 2 + 1];
                if (HAS_ADD)  { v0 += Add[idx]; v1 += Add[idx + 1]; }
                if (HAS_BIAS) { v0 += bias[cN]; v1 += bias[cN + 1]; }
                if (WRITE_RAW) { Craw[idx] = v0; Craw[idx + 1] = v1; }
                C[idx]     = RELU ? fmaxf(v0, 0.f) : v0;
                C[idx + 1] = RELU ? fmaxf(v1, 0.f) : v1;
            }
        }
    }
}

// ---------------- invnorm: 1/max(#neighbors,1) ----------------
__global__ void invnorm_kernel(const int* __restrict__ a2a, float* __restrict__ invn)
{
    int n = blockIdx.x * blockDim.x + threadIdx.x;
    if (n >= NA) return;
    int cnt = 0;
    #pragma unroll
    for (int k = 0; k < KNB; k++) cnt += (a2a[n * KNB + k] > 0) ? 1 : 0;
    invn[n] = 1.f / (float)max(cnt, 1);
}

// ---------------- pad f_atoms to stride 136 ----------------
__global__ void pad_fa_kernel(const float* __restrict__ fa, float* __restrict__ out)
{
    for (long idx = (long)blockIdx.x * blockDim.x + threadIdx.x; idx < (long)NA * FDP;
         idx += (long)gridDim.x * blockDim.x) {
        int n = (int)(idx / FDP);
        int j = (int)(idx % FDP);
        out[idx] = (j < FD) ? fa[(size_t)n * FD + j] : 0.f;
    }
}

// ---------------- X[n,c,:] (stride F2P, pads zeroed) ----------------
__global__ void build_X_kernel(const float* __restrict__ f_atoms, const float* __restrict__ f_bonds,
                               const int* __restrict__ a2a, const int* __restrict__ a2b,
                               float* __restrict__ X)
{
    int n = blockIdx.x;
    __shared__ int   nb[KNB];
    __shared__ float bond[KNB][3];
    if (threadIdx.x < KNB) {
        int k = threadIdx.x;
        nb[k] = a2a[n * KNB + k];
        int b = a2b[n * KNB + k];
        bond[k][0] = f_bonds[(size_t)b * 3 + 0];
        bond[k][1] = f_bonds[(size_t)b * 3 + 1];
        bond[k][2] = f_bonds[(size_t)b * 3 + 2];
    }
    __syncthreads();
    float ms0 = 0.f, ms1 = 0.f, ms2 = 0.f;
    #pragma unroll
    for (int k = 0; k < KNB; k++) {
        float mk = (nb[k] > 0) ? 1.f : 0.f;
        ms0 += mk * bond[k][0];
        ms1 += mk * bond[k][1];
        ms2 += mk * bond[k][2];
    }
    size_t base = (size_t)n * 3 * F2P;
    if (threadIdx.x < 18) {
        int c = threadIdx.x / 6, j = threadIdx.x % 6;
        X[base + c * F2P + F2 + j] = 0.f;
    }
    for (int f = threadIdx.x; f < FD; f += blockDim.x) {
        float selfv = f_atoms[(size_t)n * FD + f];
        float a0 = 0.f, a1 = 0.f, a2 = 0.f;
        #pragma unroll
        for (int k = 0; k < KNB; k++) {
            float fv = f_atoms[(size_t)nb[k] * FD + f];
            a0 += fv * bond[k][0];
            a1 += fv * bond[k][1];
            a2 += fv * bond[k][2];
        }
        X[base + 0 * F2P + f] = a0;
        X[base + 1 * F2P + f] = a1;
        X[base + 2 * F2P + f] = a2;
        X[base + 0 * F2P + FD + f] = selfv * ms0;
        X[base + 1 * F2P + FD + f] = selfv * ms1;
        X[base + 2 * F2P + FD + f] = selfv * ms2;
    }
}

// ---------------- neighbor gather-sum ----------------
template<bool DIVV>
__global__ void gather_kernel(const float* __restrict__ s, const float* __restrict__ v,
                              const int* __restrict__ a2a, const float* __restrict__ invn,
                              float* __restrict__ sagg, float* __restrict__ vagg)
{
    int n = blockIdx.x;
    __shared__ int nb[KNB];
    __shared__ float invsh;
    if (threadIdx.x < KNB) nb[threadIdx.x] = a2a[n * KNB + threadIdx.x];
    if (threadIdx.x == KNB) invsh = invn[n];
    __syncthreads();
    size_t b0 = (size_t)nb[0] * HD, b1 = (size_t)nb[1] * HD, b2 = (size_t)nb[2] * HD;
    size_t b3 = (size_t)nb[3] * HD, b4 = (size_t)nb[4] * HD, b5 = (size_t)nb[5] * HD;
    for (int h = threadIdx.x; h < HD; h += blockDim.x) {
        float acc = s[b0 + h] + s[b1 + h] + s[b2 + h] + s[b3 + h] + s[b4 + h] + s[b5 + h];
        sagg[(size_t)n * HD + h] = acc;
    }
    float sc = DIVV ? invsh : 1.f;
    size_t c0 = b0 * 3, c1 = b1 * 3, c2 = b2 * 3, c3 = b3 * 3, c4 = b4 * 3, c5 = b5 * 3;
    for (int e = threadIdx.x; e < 3 * HD; e += blockDim.x) {
        float acc = v[c0 + e] + v[c1 + e] + v[c2 + e] + v[c3 + e] + v[c4 + e] + v[c5 + e];
        vagg[(size_t)n * 3 * HD + e] = acc * sc;
    }
}

// ---------------- concat builders ----------------
__global__ void build_osin_kernel(const float* __restrict__ fa, const float* __restrict__ sagg,
                                  float* __restrict__ osin)
{
    for (long idx = (long)blockIdx.x * blockDim.x + threadIdx.x; idx < (long)NA * OSKP;
         idx += (long)gridDim.x * blockDim.x) {
        int n = (int)(idx / OSKP);
        int j = (int)(idx % OSKP);
        float v;
        if (j < FD)       v = fa[(size_t)n * FD + j];
        else if (j < OSK) v = sagg[(size_t)n * HD + (j - FD)];
        else              v = 0.f;
        osin[idx] = v;
    }
}

__global__ void build_ovin_kernel(const float* __restrict__ vi, const float* __restrict__ vagg,
                                  float* __restrict__ ovin)
{
    for (long idx = (long)blockIdx.x * blockDim.x + threadIdx.x; idx < (long)NA * 3 * OVK;
         idx += (long)gridDim.x * blockDim.x) {
        long r = idx / OVK;          // row (n*3+c)
        int  j = (int)(idx % OVK);
        ovin[idx] = (j < HD) ? vi[r * HD + j] : vagg[r * HD + (j - HD)];
    }
}

// o[n] = [os_[n] | sum_c ov[n,c,:]]
__global__ void build_o_kernel(const float* __restrict__ osb, const float* __restrict__ ovb,
                               float* __restrict__ o)
{
    for (long idx = (long)blockIdx.x * blockDim.x + threadIdx.x; idx < (long)NA * FFK;
         idx += (long)gridDim.x * blockDim.x) {
        int n = (int)(idx / FFK);
        int j = (int)(idx % FFK);
        if (j < FHD) {
            o[idx] = osb[(size_t)n * FHD + j];
        } else {
            int jj = j - FHD;
            size_t b = (size_t)n * 3 * FHD + jj;
            o[idx] = ovb[b] + ovb[b + FHD] + ovb[b + 2 * FHD];
        }
    }
}

// ---------------- readout ----------------
__global__ void mol_start_kernel(const int* __restrict__ ids, int* __restrict__ start)
{
    int m = blockIdx.x * blockDim.x + threadIdx.x;
    if (m > NM) return;
    int lo = 0, hi = NA;
    while (lo < hi) {
        int mid = (lo + hi) >> 1;
        if (ids[mid] < m) lo = mid + 1; else hi = mid;
    }
    start[m] = lo;
}

__global__ void segment_mean_kernel(const float* __restrict__ o, const int* __restrict__ start,
                                    float* __restrict__ mol)
{
    int m = blockIdx.x;
    int s0 = start[m], e0 = start[m + 1];
    int cnt = e0 - s0;
    if (s0 == 0 && e0 > 0) cnt -= 1;   // atom 0 is padding
    float sc = 1.f / (float)max(cnt, 1);
    for (int f = threadIdx.x; f < FFK; f += blockDim.x) {
        float acc = 0.f;
        for (int n = s0; n < e0; n++) {
            if (n == 0) continue;
            acc += o[(size_t)n * FFK + f];
        }
        mol[m * FFK + f] = acc * sc;
    }
}

__global__ void ffn_out_kernel(const float* __restrict__ h, const float* __restrict__ W2,
                               const float* __restrict__ b2, float* __restrict__ out)
{
    int m = blockIdx.x;
    float acc = 0.f;
    for (int j = threadIdx.x; j < FHD; j += 256) acc += h[m * FHD + j] * W2[j];
    __shared__ float red[256];
    red[threadIdx.x] = acc;
    __syncthreads();
    for (int st = 128; st > 0; st >>= 1) {
        if (threadIdx.x < st) red[threadIdx.x] += red[threadIdx.x + st];
        __syncthreads();
    }
    if (threadIdx.x == 0) out[m] = red[0] + b2[0];
}

// ---------------- launch ----------------
extern "C" void kernel_launch(void* const* d_in, const int* in_sizes, int n_in,
                              void* d_out, int out_size)
{
    const float* f_atoms = (const float*)d_in[0];
    const float* f_bonds = (const float*)d_in[1];
    const float* W_is    = (const float*)d_in[2];
    const float* W_iv    = (const float*)d_in[3];
    const float* W_hs    = (const float*)d_in[4];
    const float* W_hv    = (const float*)d_in[5];
    const float* W_os    = (const float*)d_in[6];
    const float* b_os    = (const float*)d_in[7];
    const float* W_ov    = (const float*)d_in[8];
    const float* b_ov    = (const float*)d_in[9];
    const float* ffn_W1  = (const float*)d_in[10];
    const float* ffn_b1  = (const float*)d_in[11];
    const float* ffn_W2  = (const float*)d_in[12];
    const float* ffn_b2  = (const float*)d_in[13];
    const int*   a2a     = (const int*)d_in[14];
    const int*   a2b     = (const int*)d_in[15];
    const int*   mol_ids = (const int*)d_in[16];
    float*       out     = (float*)d_out;

    float *p_fap, *p_si, *p_s, *p_sagg, *p_vi, *p_v, *p_vagg, *p_X, *p_osin, *p_ovin;
    float *p_osb, *p_ovb, *p_o, *p_mol, *p_h, *p_invn;
    int* p_molstart;
    cudaGetSymbolAddress((void**)&p_fap,  g_fapad);
    cudaGetSymbolAddress((void**)&p_si,   g_si);
    cudaGetSymbolAddress((void**)&p_s,    g_s);
    cudaGetSymbolAddress((void**)&p_sagg, g_sagg);
    cudaGetSymbolAddress((void**)&p_vi,   g_vi);
    cudaGetSymbolAddress((void**)&p_v,    g_v);
    cudaGetSymbolAddress((void**)&p_vagg, g_vagg);
    cudaGetSymbolAddress((void**)&p_X,    g_X);
    cudaGetSymbolAddress((void**)&p_osin, g_osin);
    cudaGetSymbolAddress((void**)&p_ovin, g_ovin);
    cudaGetSymbolAddress((void**)&p_osb,  g_osb);
    cudaGetSymbolAddress((void**)&p_ovb,  g_ovb);
    cudaGetSymbolAddress((void**)&p_o,    g_o);
    cudaGetSymbolAddress((void**)&p_mol,  g_mol);
    cudaGetSymbolAddress((void**)&p_h,    g_h);
    cudaGetSymbolAddress((void**)&p_invn, g_invn);
    cudaGetSymbolAddress((void**)&p_molstart, g_molstart);

    // 1. prep
    invnorm_kernel<<<(NA + 255) / 256, 256>>>(a2a, p_invn);
    pad_fa_kernel<<<2048, 256>>>(f_atoms, p_fap);
    build_X_kernel<<<NA, 128>>>(f_atoms, f_bonds, a2a, a2b, p_X);

    // 2. si = f_atoms @ W_is (raw -> g_si, relu -> g_s)
    dim3 gsi((HD + BN - 1) / BN, (NA + BM - 1) / BM);
    tgemm_kernel<true, false, false, true><<<gsi, 256>>>(
        p_fap, W_is, nullptr, nullptr, p_s, p_si, NA, HD, FD, FDP, FDP);

    // 3. vi = X @ W_iv
    dim3 gvi((HD + BN - 1) / BN, (3 * NA + BM - 1) / BM);
    tgemm_kernel<true, false, false, true><<<gvi, 256>>>(
        p_X, W_iv, nullptr, nullptr, p_v, p_vi, 3 * NA, HD, F2, F2P, F2P);

    // 4. message passing
    for (int it = 0; it < 6; it++) {
        gather_kernel<true><<<NA, 256>>>(p_s, p_v, a2a, p_invn, p_sagg, p_vagg);
        tgemm_kernel<true, true, false, false><<<gsi, 256>>>(
            p_sagg, W_hs, p_si, nullptr, p_s, nullptr, NA, HD, HD, HD, HD);
        tgemm_kernel<true, true, false, false><<<gvi, 256>>>(
            p_vagg, W_hv, p_vi, nullptr, p_v, nullptr, 3 * NA, HD, HD, HD, HD);
    }

    // 5. output stage
    gather_kernel<false><<<NA, 256>>>(p_s, p_v, a2a, p_invn, p_sagg, p_vagg);
    {
        long tot1 = (long)NA * OSKP;
        build_osin_kernel<<<(unsigned)((tot1 + 255) / 256), 256>>>(f_atoms, p_sagg, p_osin);
        long tot2 = (long)NA * 3 * OVK;
        build_ovin_kernel<<<(unsigned)((tot2 + 255) / 256), 256>>>(p_vi, p_vagg, p_ovin);
    }
    dim3 gos((FHD + BN - 1) / BN, (NA + BM - 1) / BM);
    tgemm_kernel<true, false, true, false><<<gos, 256>>>(
        p_osin, W_os, nullptr, b_os, p_osb, nullptr, NA, FHD, OSK, OSKP, OSKP);
    dim3 gov((FHD + BN - 1) / BN, (3 * NA + BM - 1) / BM);
    tgemm_kernel<true, false, true, false><<<gov, 256>>>(
        p_ovin, W_ov, nullptr, b_ov, p_ovb, nullptr, 3 * NA, FHD, OVK, OVK, OVK);
    {
        long tot3 = (long)NA * FFK;
        build_o_kernel<<<(unsigned)((tot3 + 255) / 256), 256>>>(p_osb, p_ovb, p_o);
    }

    // 6. readout + FFN
    mol_start_kernel<<<4, 256>>>(mol_ids, p_molstart);
    segment_mean_kernel<<<NM, 256>>>(p_o, p_molstart, p_mol);
    dim3 gff((FHD + BN - 1) / BN, (NM + BM - 1) / BM);
    tgemm_kernel<true, false, true, false><<<gff, 256>>>(
        p_mol, ffn_W1, nullptr, ffn_b1, p_h, nullptr, NM, FHD, FFK, FFK, FFK);
    ffn_out_kernel<<<NM, 256>>>(p_h, ffn_W2, ffn_b2, out);
}

// round 5
// speedup vs baseline: 1.6785x; 1.3188x over previous
#include <cuda_runtime.h>

// ---------------- Problem constants ----------------
#define NA   20001      // atoms (incl padding atom 0)
#define FD   133        // atom feature dim
#define KNB  6          // max neighbors
#define HD   1100       // hidden dim
#define FHD  700        // ffn hidden dim
#define NM   800        // molecules
#define F2   266        // 2*FD
#define OSK  1233       // FD + HD
#define OVK  2200       // 2*HD
#define FFK  1400       // 2*FHD

// padded A-side strides (16B-aligned rows for cp.async)
#define FDP  136        // f_atoms padded
#define F2P  272        // X padded
#define OSKP 1236       // osin padded

// ---------------- Scratch (device globals: allocation-free) ----------------
__device__ __align__(16) float g_fapad[(size_t)NA * FDP];
__device__ __align__(16) float g_si  [(size_t)NA * HD];
__device__ __align__(16) float g_s   [(size_t)NA * HD];
__device__ __align__(16) float g_sagg[(size_t)NA * HD];
__device__ __align__(16) float g_vi  [(size_t)NA * 3 * HD];
__device__ __align__(16) float g_v   [(size_t)NA * 3 * HD];
__device__ __align__(16) float g_vagg[(size_t)NA * 3 * HD];
__device__ __align__(16) float g_X   [(size_t)NA * 3 * F2P];
__device__ __align__(16) float g_osin[(size_t)NA * OSKP];
__device__ __align__(16) float g_ovin[(size_t)NA * 3 * OVK];
__device__ __align__(16) float g_osb [(size_t)NA * FHD];
__device__ __align__(16) float g_ovb [(size_t)NA * 3 * FHD];
__device__ __align__(16) float g_o   [(size_t)NA * FFK];
__device__ __align__(16) float g_mol [NM * FFK];
__device__ __align__(16) float g_h   [NM * FHD];
__device__ __align__(16) float g_invn[NA];
__device__ int   g_molstart[NM + 1];

// ---------------- TF32x3 tensor-core GEMM (fp32-accurate) ----------------
// C[M,N] = act(A[M,Kd] @ B[Kd,N] [+ Add] [+ bias])
// Split x = hi + lo: hi = tf32_rna(x) (valid fp32, low 13 bits clear),
// lo = (x - hi) passed raw (HW truncates to tf32; err ~2^-21 — negligible).
// acc += a_hi*b_lo + a_lo*b_hi + a_hi*b_hi.

#define BM 128
#define BN 128
#define BK 16
#define AST 20    // A smem row stride (floats): conflict-free fragment reads
#define BST 136   // B smem row stride (floats)

__device__ __forceinline__ void tf32split(float x, unsigned& hi, unsigned& lo) {
    unsigned h;
    asm("cvt.rna.tf32.f32 %0, %1;\n" : "=r"(h) : "f"(x));
    float hf = __uint_as_float(h);     // exact fp32
    lo = __float_as_uint(x - hf);      // raw residual; HW reads top 19 bits (RZ)
    hi = h;
}

__device__ __forceinline__ void cp16(float* dst_smem, const float* src, int bytes) {
    unsigned sa = (unsigned)__cvta_generic_to_shared(dst_smem);
    asm volatile("cp.async.ca.shared.global [%0], [%1], 16, %2;\n"
                 :: "r"(sa), "l"(src), "r"(bytes));
}

#define MMA_TF32(ACC, AF, BF)                                                   \
    asm volatile(                                                               \
        "mma.sync.aligned.m16n8k8.row.col.f32.tf32.tf32.f32 "                   \
        "{%0,%1,%2,%3}, {%4,%5,%6,%7}, {%8,%9}, {%0,%1,%2,%3};\n"               \
        : "+f"(ACC[0]), "+f"(ACC[1]), "+f"(ACC[2]), "+f"(ACC[3])                \
        : "r"(AF[0]), "r"(AF[1]), "r"(AF[2]), "r"(AF[3]),                       \
          "r"(BF[0]), "r"(BF[1]))

template<bool RELU, bool HAS_ADD, bool HAS_BIAS, bool WRITE_RAW>
__global__ __launch_bounds__(256, 2)
void tgemm_kernel(const float* __restrict__ A, const float* __restrict__ B,
                  const float* __restrict__ Add, const float* __restrict__ bias,
                  float* __restrict__ C, float* __restrict__ Craw,
                  int M, int N, int Kd, int lda, int KA)
{
    __shared__ float As[2][BM][AST];
    __shared__ float Bs[2][BK][BST];

    const int tid = threadIdx.x;
    const int rowBase = blockIdx.y * BM;
    const int colBase = blockIdx.x * BN;
    const int warpId = tid >> 5;
    const int lane = tid & 31;
    const int g  = lane >> 2;        // group id (0..7)
    const int tg = lane & 3;         // thread-in-group (0..3)
    const int wm = (warpId & 1) * 64;
    const int wn = (warpId >> 1) * 32;

    float acc[4][4][4];
    #pragma unroll
    for (int mi = 0; mi < 4; mi++)
        #pragma unroll
        for (int ni = 0; ni < 4; ni++)
            #pragma unroll
            for (int j = 0; j < 4; j++) acc[mi][ni][j] = 0.f;

    const int T = (Kd + BK - 1) / BK;

    auto load_tile = [&](int t, int st) {
        const int kt = t * BK;
        #pragma unroll
        for (int i = 0; i < 2; i++) {
            int c = tid + i * 256;
            int m = c >> 2, kq = (c & 3) << 2;
            int gm = rowBase + m, gk = kt + kq;
            bool ok = (gm < M) && (gk < KA);
            const float* src = ok ? (A + (size_t)gm * lda + gk) : A;
            cp16(&As[st][m][kq], src, ok ? 16 : 0);
        }
        #pragma unroll
        for (int i = 0; i < 2; i++) {
            int c = tid + i * 256;
            int k = c >> 5, n = (c & 31) << 2;
            int gk = kt + k, gn = colBase + n;
            bool ok = (gk < Kd) && (gn < N);
            const float* src = ok ? (B + (size_t)gk * N + gn) : B;
            cp16(&Bs[st][k][n], src, ok ? 16 : 0);
        }
        asm volatile("cp.async.commit_group;\n");
    };

    load_tile(0, 0);
    int st = 0;

    for (int t = 0; t < T; t++) {
        if (t + 1 < T) {
            load_tile(t + 1, st ^ 1);
            asm volatile("cp.async.wait_group 1;\n");
        } else {
            asm volatile("cp.async.wait_group 0;\n");
        }
        __syncthreads();

        #pragma unroll
        for (int ks = 0; ks < 2; ks++) {
            const int k0 = ks * 8;
            unsigned ah[4][4], al[4][4], bh[4][2], bl[4][2];
            #pragma unroll
            for (int mi = 0; mi < 4; mi++) {
                int m = wm + mi * 16 + g;
                tf32split(As[st][m    ][k0 + tg    ], ah[mi][0], al[mi][0]);
                tf32split(As[st][m + 8][k0 + tg    ], ah[mi][1], al[mi][1]);
                tf32split(As[st][m    ][k0 + tg + 4], ah[mi][2], al[mi][2]);
                tf32split(As[st][m + 8][k0 + tg + 4], ah[mi][3], al[mi][3]);
            }
            #pragma unroll
            for (int ni = 0; ni < 4; ni++) {
                int n = wn + ni * 8 + g;
                tf32split(Bs[st][k0 + tg    ][n], bh[ni][0], bl[ni][0]);
                tf32split(Bs[st][k0 + tg + 4][n], bh[ni][1], bl[ni][1]);
            }
            #pragma unroll
            for (int mi = 0; mi < 4; mi++)
                #pragma unroll
                for (int ni = 0; ni < 4; ni++) {
                    MMA_TF32(acc[mi][ni], ah[mi], bl[ni]);   // hi*lo
                    MMA_TF32(acc[mi][ni], al[mi], bh[ni]);   // lo*hi
                    MMA_TF32(acc[mi][ni], ah[mi], bh[ni]);   // hi*hi (last: largest term)
                }
        }
        __syncthreads();
        st ^= 1;
    }

    // ---- epilogue ----
    #pragma unroll
    for (int mi = 0; mi < 4; mi++) {
        int r0 = rowBase + wm + mi * 16 + g;
        #pragma unroll
        for (int ni = 0; ni < 4; ni++) {
            int cN = colBase + wn + ni * 8 + tg * 2;
            if (cN >= N) continue;
            #pragma unroll
            for (int half = 0; half < 2; half++) {
                int r = r0 + half * 8;
                if (r >= M) continue;
                size_t idx = (size_t)r * N + cN;
                float v0 = acc[mi][ni][half * 2 + 0];
                float v1 = acc[mi][ni][half * 2 + 1];
                if (HAS_ADD)  { v0 += Add[idx]; v1 += Add[idx + 1]; }
                if (HAS_BIAS) { v0 += bias[cN]; v1 += bias[cN + 1]; }
                if (WRITE_RAW) { Craw[idx] = v0; Craw[idx + 1] = v1; }
                C[idx]     = RELU ? fmaxf(v0, 0.f) : v0;
                C[idx + 1] = RELU ? fmaxf(v1, 0.f) : v1;
            }
        }
    }
}

// ---------------- invnorm: 1/max(#neighbors,1) ----------------
__global__ void invnorm_kernel(const int* __restrict__ a2a, float* __restrict__ invn)
{
    int n = blockIdx.x * blockDim.x + threadIdx.x;
    if (n >= NA) return;
    int cnt = 0;
    #pragma unroll
    for (int k = 0; k < KNB; k++) cnt += (a2a[n * KNB + k] > 0) ? 1 : 0;
    invn[n] = 1.f / (float)max(cnt, 1);
}

// ---------------- pad f_atoms to stride 136 ----------------
__global__ void pad_fa_kernel(const float* __restrict__ fa, float* __restrict__ out)
{
    for (long idx = (long)blockIdx.x * blockDim.x + threadIdx.x; idx < (long)NA * FDP;
         idx += (long)gridDim.x * blockDim.x) {
        int n = (int)(idx / FDP);
        int j = (int)(idx % FDP);
        out[idx] = (j < FD) ? fa[(size_t)n * FD + j] : 0.f;
    }
}

// ---------------- X[n,c,:] (stride F2P, pads zeroed) ----------------
__global__ void build_X_kernel(const float* __restrict__ f_atoms, const float* __restrict__ f_bonds,
                               const int* __restrict__ a2a, const int* __restrict__ a2b,
                               float* __restrict__ X)
{
    int n = blockIdx.x;
    __shared__ int   nb[KNB];
    __shared__ float bond[KNB][3];
    if (threadIdx.x < KNB) {
        int k = threadIdx.x;
        nb[k] = a2a[n * KNB + k];
        int b = a2b[n * KNB + k];
        bond[k][0] = f_bonds[(size_t)b * 3 + 0];
        bond[k][1] = f_bonds[(size_t)b * 3 + 1];
        bond[k][2] = f_bonds[(size_t)b * 3 + 2];
    }
    __syncthreads();
    float ms0 = 0.f, ms1 = 0.f, ms2 = 0.f;
    #pragma unroll
    for (int k = 0; k < KNB; k++) {
        float mk = (nb[k] > 0) ? 1.f : 0.f;
        ms0 += mk * bond[k][0];
        ms1 += mk * bond[k][1];
        ms2 += mk * bond[k][2];
    }
    size_t base = (size_t)n * 3 * F2P;
    if (threadIdx.x < 18) {
        int c = threadIdx.x / 6, j = threadIdx.x % 6;
        X[base + c * F2P + F2 + j] = 0.f;
    }
    for (int f = threadIdx.x; f < FD; f += blockDim.x) {
        float selfv = f_atoms[(size_t)n * FD + f];
        float a0 = 0.f, a1 = 0.f, a2 = 0.f;
        #pragma unroll
        for (int k = 0; k < KNB; k++) {
            float fv = f_atoms[(size_t)nb[k] * FD + f];
            a0 += fv * bond[k][0];
            a1 += fv * bond[k][1];
            a2 += fv * bond[k][2];
        }
        X[base + 0 * F2P + f] = a0;
        X[base + 1 * F2P + f] = a1;
        X[base + 2 * F2P + f] = a2;
        X[base + 0 * F2P + FD + f] = selfv * ms0;
        X[base + 1 * F2P + FD + f] = selfv * ms1;
        X[base + 2 * F2P + FD + f] = selfv * ms2;
    }
}

// ---------------- neighbor gather-sum ----------------
template<bool DIVV>
__global__ void gather_kernel(const float* __restrict__ s, const float* __restrict__ v,
                              const int* __restrict__ a2a, const float* __restrict__ invn,
                              float* __restrict__ sagg, float* __restrict__ vagg)
{
    int n = blockIdx.x;
    __shared__ int nb[KNB];
    __shared__ float invsh;
    if (threadIdx.x < KNB) nb[threadIdx.x] = a2a[n * KNB + threadIdx.x];
    if (threadIdx.x == KNB) invsh = invn[n];
    __syncthreads();
    size_t b0 = (size_t)nb[0] * HD, b1 = (size_t)nb[1] * HD, b2 = (size_t)nb[2] * HD;
    size_t b3 = (size_t)nb[3] * HD, b4 = (size_t)nb[4] * HD, b5 = (size_t)nb[5] * HD;
    for (int h = threadIdx.x; h < HD; h += blockDim.x) {
        float acc = s[b0 + h] + s[b1 + h] + s[b2 + h] + s[b3 + h] + s[b4 + h] + s[b5 + h];
        sagg[(size_t)n * HD + h] = acc;
    }
    float sc = DIVV ? invsh : 1.f;
    size_t c0 = b0 * 3, c1 = b1 * 3, c2 = b2 * 3, c3 = b3 * 3, c4 = b4 * 3, c5 = b5 * 3;
    for (int e = threadIdx.x; e < 3 * HD; e += blockDim.x) {
        float acc = v[c0 + e] + v[c1 + e] + v[c2 + e] + v[c3 + e] + v[c4 + e] + v[c5 + e];
        vagg[(size_t)n * 3 * HD + e] = acc * sc;
    }
}

// ---------------- concat builders ----------------
__global__ void build_osin_kernel(const float* __restrict__ fa, const float* __restrict__ sagg,
                                  float* __restrict__ osin)
{
    for (long idx = (long)blockIdx.x * blockDim.x + threadIdx.x; idx < (long)NA * OSKP;
         idx += (long)gridDim.x * blockDim.x) {
        int n = (int)(idx / OSKP);
        int j = (int)(idx % OSKP);
        float v;
        if (j < FD)       v = fa[(size_t)n * FD + j];
        else if (j < OSK) v = sagg[(size_t)n * HD + (j - FD)];
        else              v = 0.f;
        osin[idx] = v;
    }
}

__global__ void build_ovin_kernel(const float* __restrict__ vi, const float* __restrict__ vagg,
                                  float* __restrict__ ovin)
{
    for (long idx = (long)blockIdx.x * blockDim.x + threadIdx.x; idx < (long)NA * 3 * OVK;
         idx += (long)gridDim.x * blockDim.x) {
        long r = idx / OVK;          // row (n*3+c)
        int  j = (int)(idx % OVK);
        ovin[idx] = (j < HD) ? vi[r * HD + j] : vagg[r * HD + (j - HD)];
    }
}

// o[n] = [os_[n] | sum_c ov[n,c,:]]
__global__ void build_o_kernel(const float* __restrict__ osb, const float* __restrict__ ovb,
                               float* __restrict__ o)
{
    for (long idx = (long)blockIdx.x * blockDim.x + threadIdx.x; idx < (long)NA * FFK;
         idx += (long)gridDim.x * blockDim.x) {
        int n = (int)(idx / FFK);
        int j = (int)(idx % FFK);
        if (j < FHD) {
            o[idx] = osb[(size_t)n * FHD + j];
        } else {
            int jj = j - FHD;
            size_t b = (size_t)n * 3 * FHD + jj;
            o[idx] = ovb[b] + ovb[b + FHD] + ovb[b + 2 * FHD];
        }
    }
}

// ---------------- readout ----------------
__global__ void mol_start_kernel(const int* __restrict__ ids, int* __restrict__ start)
{
    int m = blockIdx.x * blockDim.x + threadIdx.x;
    if (m > NM) return;
    int lo = 0, hi = NA;
    while (lo < hi) {
        int mid = (lo + hi) >> 1;
        if (ids[mid] < m) lo = mid + 1; else hi = mid;
    }
    start[m] = lo;
}

__global__ void segment_mean_kernel(const float* __restrict__ o, const int* __restrict__ start,
                                    float* __restrict__ mol)
{
    int m = blockIdx.x;
    int s0 = start[m], e0 = start[m + 1];
    int cnt = e0 - s0;
    if (s0 == 0 && e0 > 0) cnt -= 1;   // atom 0 is padding
    float sc = 1.f / (float)max(cnt, 1);
    for (int f = threadIdx.x; f < FFK; f += blockDim.x) {
        float acc = 0.f;
        for (int n = s0; n < e0; n++) {
            if (n == 0) continue;
            acc += o[(size_t)n * FFK + f];
        }
        mol[m * FFK + f] = acc * sc;
    }
}

__global__ void ffn_out_kernel(const float* __restrict__ h, const float* __restrict__ W2,
                               const float* __restrict__ b2, float* __restrict__ out)
{
    int m = blockIdx.x;
    float acc = 0.f;
    for (int j = threadIdx.x; j < FHD; j += 256) acc += h[m * FHD + j] * W2[j];
    __shared__ float red[256];
    red[threadIdx.x] = acc;
    __syncthreads();
    for (int st = 128; st > 0; st >>= 1) {
        if (threadIdx.x < st) red[threadIdx.x] += red[threadIdx.x + st];
        __syncthreads();
    }
    if (threadIdx.x == 0) out[m] = red[0] + b2[0];
}

// ---------------- launch ----------------
extern "C" void kernel_launch(void* const* d_in, const int* in_sizes, int n_in,
                              void* d_out, int out_size)
{
    const float* f_atoms = (const float*)d_in[0];
    const float* f_bonds = (const float*)d_in[1];
    const float* W_is    = (const float*)d_in[2];
    const float* W_iv    = (const float*)d_in[3];
    const float* W_hs    = (const float*)d_in[4];
    const float* W_hv    = (const float*)d_in[5];
    const float* W_os    = (const float*)d_in[6];
    const float* b_os    = (const float*)d_in[7];
    const float* W_ov    = (const float*)d_in[8];
    const float* b_ov    = (const float*)d_in[9];
    const float* ffn_W1  = (const float*)d_in[10];
    const float* ffn_b1  = (const float*)d_in[11];
    const float* ffn_W2  = (const float*)d_in[12];
    const float* ffn_b2  = (const float*)d_in[13];
    const int*   a2a     = (const int*)d_in[14];
    const int*   a2b     = (const int*)d_in[15];
    const int*   mol_ids = (const int*)d_in[16];
    float*       out     = (float*)d_out;

    float *p_fap, *p_si, *p_s, *p_sagg, *p_vi, *p_v, *p_vagg, *p_X, *p_osin, *p_ovin;
    float *p_osb, *p_ovb, *p_o, *p_mol, *p_h, *p_invn;
    int* p_molstart;
    cudaGetSymbolAddress((void**)&p_fap,  g_fapad);
    cudaGetSymbolAddress((void**)&p_si,   g_si);
    cudaGetSymbolAddress((void**)&p_s,    g_s);
    cudaGetSymbolAddress((void**)&p_sagg, g_sagg);
    cudaGetSymbolAddress((void**)&p_vi,   g_vi);
    cudaGetSymbolAddress((void**)&p_v,    g_v);
    cudaGetSymbolAddress((void**)&p_vagg, g_vagg);
    cudaGetSymbolAddress((void**)&p_X,    g_X);
    cudaGetSymbolAddress((void**)&p_osin, g_osin);
    cudaGetSymbolAddress((void**)&p_ovin, g_ovin);
    cudaGetSymbolAddress((void**)&p_osb,  g_osb);
    cudaGetSymbolAddress((void**)&p_ovb,  g_ovb);
    cudaGetSymbolAddress((void**)&p_o,    g_o);
    cudaGetSymbolAddress((void**)&p_mol,  g_mol);
    cudaGetSymbolAddress((void**)&p_h,    g_h);
    cudaGetSymbolAddress((void**)&p_invn, g_invn);
    cudaGetSymbolAddress((void**)&p_molstart, g_molstart);

    // 1. prep
    invnorm_kernel<<<(NA + 255) / 256, 256>>>(a2a, p_invn);
    pad_fa_kernel<<<2048, 256>>>(f_atoms, p_fap);
    build_X_kernel<<<NA, 128>>>(f_atoms, f_bonds, a2a, a2b, p_X);

    // 2. si = f_atoms @ W_is (raw -> g_si, relu -> g_s)
    dim3 gsi((HD + BN - 1) / BN, (NA + BM - 1) / BM);
    tgemm_kernel<true, false, false, true><<<gsi, 256>>>(
        p_fap, W_is, nullptr, nullptr, p_s, p_si, NA, HD, FD, FDP, FDP);

    // 3. vi = X @ W_iv
    dim3 gvi((HD + BN - 1) / BN, (3 * NA + BM - 1) / BM);
    tgemm_kernel<true, false, false, true><<<gvi, 256>>>(
        p_X, W_iv, nullptr, nullptr, p_v, p_vi, 3 * NA, HD, F2, F2P, F2P);

    // 4. message passing
    for (int it = 0; it < 6; it++) {
        gather_kernel<true><<<NA, 256>>>(p_s, p_v, a2a, p_invn, p_sagg, p_vagg);
        tgemm_kernel<true, true, false, false><<<gsi, 256>>>(
            p_sagg, W_hs, p_si, nullptr, p_s, nullptr, NA, HD, HD, HD, HD);
        tgemm_kernel<true, true, false, false><<<gvi, 256>>>(
            p_vagg, W_hv, p_vi, nullptr, p_v, nullptr, 3 * NA, HD, HD, HD, HD);
    }

    // 5. output stage
    gather_kernel<false><<<NA, 256>>>(p_s, p_v, a2a, p_invn, p_sagg, p_vagg);
    {
        long tot1 = (long)NA * OSKP;
        build_osin_kernel<<<(unsigned)((tot1 + 255) / 256), 256>>>(f_atoms, p_sagg, p_osin);
        long tot2 = (long)NA * 3 * OVK;
        build_ovin_kernel<<<(unsigned)((tot2 + 255) / 256), 256>>>(p_vi, p_vagg, p_ovin);
    }
    dim3 gos((FHD + BN - 1) / BN, (NA + BM - 1) / BM);
    tgemm_kernel<true, false, true, false><<<gos, 256>>>(
        p_osin, W_os, nullptr, b_os, p_osb, nullptr, NA, FHD, OSK, OSKP, OSKP);
    dim3 gov((FHD + BN - 1) / BN, (3 * NA + BM - 1) / BM);
    tgemm_kernel<true, false, true, false><<<gov, 256>>>(
        p_ovin, W_ov, nullptr, b_ov, p_ovb, nullptr, 3 * NA, FHD, OVK, OVK, OVK);
    {
        long tot3 = (long)NA * FFK;
        build_o_kernel<<<(unsigned)((tot3 + 255) / 256), 256>>>(p_osb, p_ovb, p_o);
    }

    // 6. readout + FFN
    mol_start_kernel<<<4, 256>>>(mol_ids, p_molstart);
    segment_mean_kernel<<<NM, 256>>>(p_o, p_molstart, p_mol);
    dim3 gff((FHD + BN - 1) / BN, (NM + BM - 1) / BM);
    tgemm_kernel<true, false, true, false><<<gff, 256>>>(
        p_mol, ffn_W1, nullptr, ffn_b1, p_h, nullptr, NM, FHD, FFK, FFK, FFK);
    ffn_out_kernel<<<NM, 256>>>(p_h, ffn_W2, ffn_b2, out);
}

// round 6
// speedup vs baseline: 2.4428x; 1.4554x over previous
#include <cuda_runtime.h>
#include <cstdint>

// ---------------- Problem constants ----------------
#define NA   20001
#define FD   133
#define KNB  6
#define HD   1100
#define FHD  700
#define NM   800
#define FFK  1400       // 2*FHD

// padded K-pair counts (multiples of 8; zero-filled pads)
#define JP_FA   72      // si : K=133→134, 67 pairs → 72  (T=9)
#define JP_X    136     // vi : K=266→268, 134 pairs → 136 (T=17)
#define JP_H    552     // hs/hv: K=1100, 550 pairs → 552 (T=69)
#define JP_OS   624     // os : K=1233→1234, 617 → 624 (T=78)
#define JP_OV   1104    // ov : K=2200, 1100 → 1104 (T=138)
#define JP_FF   704     // ffn: K=1400, 700 → 704 (T=88)

// ---------------- Scratch (device globals) ----------------
__device__ __align__(16) uint2 g_fa_p  [(size_t)NA * JP_FA];
__device__ __align__(16) uint2 g_X_p   [(size_t)NA * 3 * JP_X];
__device__ __align__(16) uint2 g_sagg_p[(size_t)NA * JP_H];
__device__ __align__(16) uint2 g_vagg_p[(size_t)NA * 3 * JP_H];
__device__ __align__(16) uint2 g_osin_p[(size_t)NA * JP_OS];
__device__ __align__(16) uint2 g_ovin_p[(size_t)NA * 3 * JP_OV];
__device__ __align__(16) uint2 g_mol_p [(size_t)NM * JP_FF];

__device__ __align__(16) uint2 g_Wis_p [(size_t)JP_FA * HD];
__device__ __align__(16) uint2 g_Wiv_p [(size_t)JP_X  * HD];
__device__ __align__(16) uint2 g_Whs_p [(size_t)JP_H  * HD];
__device__ __align__(16) uint2 g_Whv_p [(size_t)JP_H  * HD];
__device__ __align__(16) uint2 g_Wos_p [(size_t)JP_OS * FHD];
__device__ __align__(16) uint2 g_Wov_p [(size_t)JP_OV * FHD];
__device__ __align__(16) uint2 g_Wff_p [(size_t)JP_FF * FHD];

__device__ __align__(16) float g_si [(size_t)NA * HD];
__device__ __align__(16) float g_s  [(size_t)NA * HD];
__device__ __align__(16) float g_vi [(size_t)NA * 3 * HD];
__device__ __align__(16) float g_v  [(size_t)NA * 3 * HD];
__device__ __align__(16) float g_osb[(size_t)NA * FHD];
__device__ __align__(16) float g_ovb[(size_t)NA * 3 * FHD];
__device__ __align__(16) float g_o  [(size_t)NA * FFK];
__device__ __align__(16) float g_h  [NM * FHD];
__device__ __align__(16) float g_invn[NA];
__device__ int g_molstart[NM + 1];

// ---------------- bf16 split-pack helper ----------------
// returns {hi_pair, lo_pair}; each pair = bf16x2 {lo16 = x0, hi16 = x1}
__device__ __forceinline__ uint2 splitpack(float x0, float x1) {
    unsigned h;
    asm("cvt.rn.bf16x2.f32 %0, %1, %2;" : "=r"(h) : "f"(x1), "f"(x0));
    float h0 = __uint_as_float(h << 16);
    float h1 = __uint_as_float(h & 0xFFFF0000u);
    unsigned l;
    asm("cvt.rn.bf16x2.f32 %0, %1, %2;" : "=r"(l) : "f"(x1 - h1), "f"(x0 - h0));
    return make_uint2(h, l);
}

__device__ __forceinline__ void cp16(void* dst_smem, const void* src, int bytes) {
    unsigned sa = (unsigned)__cvta_generic_to_shared(dst_smem);
    asm volatile("cp.async.ca.shared.global [%0], [%1], 16, %2;\n"
                 :: "r"(sa), "l"(src), "r"(bytes));
}

#define MMA_BF16(ACC, AF, BF)                                                   \
    asm volatile(                                                               \
        "mma.sync.aligned.m16n8k16.row.col.f32.bf16.bf16.f32 "                  \
        "{%0,%1,%2,%3}, {%4,%5,%6,%7}, {%8,%9}, {%0,%1,%2,%3};\n"               \
        : "+f"(ACC[0]), "+f"(ACC[1]), "+f"(ACC[2]), "+f"(ACC[3])                \
        : "r"(AF[0]), "r"(AF[1]), "r"(AF[2]), "r"(AF[3]),                       \
          "r"(BF[0]), "r"(BF[1]))

// ---------------- bf16x3 GEMM ----------------
// C[M,N] = act(A@B [+Add] [+bias]); A,B pre-split packed-pair planes.
// A_p[m][j] = {hi(x_{2j},x_{2j+1}), lo(...)}, lda_p pairs per row (= T*8).
// B_p[j][n] similarly, row stride N. All pads zero-filled.
#define BM 128
#define BN 128
#define ASTP 10    // A smem row stride in uint2
#define BSTP 132   // B smem row stride in uint2

template<bool RELU, bool HAS_ADD, bool HAS_BIAS, bool WRITE_RAW>
__global__ __launch_bounds__(256, 2)
void bgemm_kernel(const uint2* __restrict__ A, const uint2* __restrict__ B,
                  const float* __restrict__ Add, const float* __restrict__ bias,
                  float* __restrict__ C, float* __restrict__ Craw,
                  int M, int N, int T, int lda_p)
{
    __shared__ uint2 As[2][BM][ASTP];
    __shared__ uint2 Bs[2][8][BSTP];

    const int tid = threadIdx.x;
    const int rowBase = blockIdx.y * BM;
    const int colBase = blockIdx.x * BN;
    const int warpId = tid >> 5;
    const int lane = tid & 31;
    const int g  = lane >> 2;
    const int tg = lane & 3;
    const int wm = (warpId & 1) * 64;
    const int wn = (warpId >> 1) * 32;

    float acc[4][4][4];
    #pragma unroll
    for (int mi = 0; mi < 4; mi++)
        #pragma unroll
        for (int ni = 0; ni < 4; ni++)
            #pragma unroll
            for (int j = 0; j < 4; j++) acc[mi][ni][j] = 0.f;

    auto load_tile = [&](int t, int st) {
        const int jt = t * 8;
        #pragma unroll
        for (int i = 0; i < 2; i++) {       // A: 512 chunks of 16B (2 uint2)
            int c = tid + i * 256;
            int m = c >> 2, q = (c & 3) << 1;
            int gm = rowBase + m;
            bool ok = gm < M;
            const uint2* src = ok ? (A + (size_t)gm * lda_p + jt + q) : A;
            cp16(&As[st][m][q], src, ok ? 16 : 0);
        }
        #pragma unroll
        for (int i = 0; i < 2; i++) {       // B: 512 chunks (2 cols)
            int c = tid + i * 256;
            int j = c >> 6, n = (c & 63) << 1;
            int gn = colBase + n;
            bool ok = gn < N;
            const uint2* src = ok ? (B + (size_t)(jt + j) * N + gn) : B;
            cp16(&Bs[st][j][n], src, ok ? 16 : 0);
        }
        asm volatile("cp.async.commit_group;\n");
    };

    load_tile(0, 0);
    int st = 0;

    for (int t = 0; t < T; t++) {
        if (t + 1 < T) {
            load_tile(t + 1, st ^ 1);
            asm volatile("cp.async.wait_group 1;\n");
        } else {
            asm volatile("cp.async.wait_group 0;\n");
        }
        __syncthreads();

        unsigned ah[4][4], al[4][4], bh[4][2], bl[4][2];
        #pragma unroll
        for (int mi = 0; mi < 4; mi++) {
            int r = wm + mi * 16 + g;
            uint2 p0 = As[st][r    ][tg];
            uint2 p1 = As[st][r + 8][tg];
            uint2 p2 = As[st][r    ][4 + tg];
            uint2 p3 = As[st][r + 8][4 + tg];
            ah[mi][0] = p0.x; ah[mi][1] = p1.x; ah[mi][2] = p2.x; ah[mi][3] = p3.x;
            al[mi][0] = p0.y; al[mi][1] = p1.y; al[mi][2] = p2.y; al[mi][3] = p3.y;
        }
        #pragma unroll
        for (int ni = 0; ni < 4; ni++) {
            int n = wn + ni * 8 + g;
            uint2 q0 = Bs[st][tg    ][n];
            uint2 q1 = Bs[st][4 + tg][n];
            bh[ni][0] = q0.x; bh[ni][1] = q1.x;
            bl[ni][0] = q0.y; bl[ni][1] = q1.y;
        }
        #pragma unroll
        for (int mi = 0; mi < 4; mi++)
            #pragma unroll
            for (int ni = 0; ni < 4; ni++) {
                MMA_BF16(acc[mi][ni], ah[mi], bl[ni]);   // hi*lo
                MMA_BF16(acc[mi][ni], al[mi], bh[ni]);   // lo*hi
                MMA_BF16(acc[mi][ni], ah[mi], bh[ni]);   // hi*hi last
            }
        __syncthreads();
        st ^= 1;
    }

    #pragma unroll
    for (int mi = 0; mi < 4; mi++) {
        int r0 = rowBase + wm + mi * 16 + g;
        #pragma unroll
        for (int ni = 0; ni < 4; ni++) {
            int cN = colBase + wn + ni * 8 + tg * 2;
            if (cN >= N) continue;
            #pragma unroll
            for (int half = 0; half < 2; half++) {
                int r = r0 + half * 8;
                if (r >= M) continue;
                size_t idx = (size_t)r * N + cN;
                float v0 = acc[mi][ni][half * 2 + 0];
                float v1 = acc[mi][ni][half * 2 + 1];
                if (HAS_ADD)  { v0 += Add[idx]; v1 += Add[idx + 1]; }
                if (HAS_BIAS) { v0 += bias[cN]; v1 += bias[cN + 1]; }
                if (WRITE_RAW) { Craw[idx] = v0; Craw[idx + 1] = v1; }
                C[idx]     = RELU ? fmaxf(v0, 0.f) : v0;
                C[idx + 1] = RELU ? fmaxf(v1, 0.f) : v1;
            }
        }
    }
}

// ---------------- weight split-pack (2-segment k remap) ----------------
__global__ void packW_kernel(const float* __restrict__ W, int N, int Jtot,
                             int s0, int l0, int d0, int s1, int l1, int d1,
                             uint2* __restrict__ out)
{
    long tot = (long)Jtot * N;
    for (long idx = (long)blockIdx.x * blockDim.x + threadIdx.x; idx < tot;
         idx += (long)gridDim.x * blockDim.x) {
        int j = (int)(idx / N), n = (int)(idx % N);
        float v[2];
        #pragma unroll
        for (int e = 0; e < 2; e++) {
            int k = 2 * j + e, row = -1;
            if (k >= d1 && k < d1 + l1) row = s1 + (k - d1);
            else if (k >= d0 && k < d0 + l0) row = s0 + (k - d0);
            v[e] = (row < 0) ? 0.f : W[(size_t)row * N + n];
        }
        out[idx] = splitpack(v[0], v[1]);
    }
}

// ---------------- invnorm ----------------
__global__ void invnorm_kernel(const int* __restrict__ a2a, float* __restrict__ invn)
{
    int n = blockIdx.x * blockDim.x + threadIdx.x;
    if (n >= NA) return;
    int cnt = 0;
    #pragma unroll
    for (int k = 0; k < KNB; k++) cnt += (a2a[n * KNB + k] > 0) ? 1 : 0;
    invn[n] = 1.f / (float)max(cnt, 1);
}

// ---------------- f_atoms -> packed (k padded to 134) ----------------
__global__ void pack_fa_kernel(const float* __restrict__ fa, uint2* __restrict__ out)
{
    long tot = (long)NA * JP_FA;
    for (long idx = (long)blockIdx.x * blockDim.x + threadIdx.x; idx < tot;
         idx += (long)gridDim.x * blockDim.x) {
        int n = (int)(idx / JP_FA), j = (int)(idx % JP_FA);
        int k0 = 2 * j;
        float v0 = (k0     < FD) ? fa[(size_t)n * FD + k0]     : 0.f;
        float v1 = (k0 + 1 < FD) ? fa[(size_t)n * FD + k0 + 1] : 0.f;
        out[idx] = splitpack(v0, v1);
    }
}

// ---------------- build X packed: rows (n*3+c), K layout [a(134)|self(134)] ----------------
__global__ void build_X_kernel(const float* __restrict__ f_atoms, const float* __restrict__ f_bonds,
                               const int* __restrict__ a2a, const int* __restrict__ a2b,
                               uint2* __restrict__ Xp)
{
    int n = blockIdx.x;
    __shared__ int   nb[KNB];
    __shared__ float bond[KNB][3];
    __shared__ float stg[6][134];   // [c]=a, [3+c]=self
    if (threadIdx.x < KNB) {
        int k = threadIdx.x;
        nb[k] = a2a[n * KNB + k];
        int b = a2b[n * KNB + k];
        bond[k][0] = f_bonds[(size_t)b * 3 + 0];
        bond[k][1] = f_bonds[(size_t)b * 3 + 1];
        bond[k][2] = f_bonds[(size_t)b * 3 + 2];
    }
    if (threadIdx.x < 6) stg[threadIdx.x][133] = 0.f;
    __syncthreads();
    float ms0 = 0.f, ms1 = 0.f, ms2 = 0.f;
    #pragma unroll
    for (int k = 0; k < KNB; k++) {
        float mk = (nb[k] > 0) ? 1.f : 0.f;
        ms0 += mk * bond[k][0];
        ms1 += mk * bond[k][1];
        ms2 += mk * bond[k][2];
    }
    for (int f = threadIdx.x; f < FD; f += blockDim.x) {
        float selfv = f_atoms[(size_t)n * FD + f];
        float a0 = 0.f, a1 = 0.f, a2 = 0.f;
        #pragma unroll
        for (int k = 0; k < KNB; k++) {
            float fv = f_atoms[(size_t)nb[k] * FD + f];
            a0 += fv * bond[k][0];
            a1 += fv * bond[k][1];
            a2 += fv * bond[k][2];
        }
        stg[0][f] = a0; stg[1][f] = a1; stg[2][f] = a2;
        stg[3][f] = selfv * ms0; stg[4][f] = selfv * ms1; stg[5][f] = selfv * ms2;
    }
    __syncthreads();
    for (int t = threadIdx.x; t < 3 * JP_X; t += blockDim.x) {
        int c = t / JP_X, j = t % JP_X;
        float v[2];
        #pragma unroll
        for (int e = 0; e < 2; e++) {
            int k = 2 * j + e;
            if (k < 134)      v[e] = stg[c][k];
            else if (k < 268) v[e] = stg[3 + c][k - 134];
            else              v[e] = 0.f;
        }
        Xp[((size_t)n * 3 + c) * JP_X + j] = splitpack(v[0], v[1]);
    }
}

// ---------------- message-passing gather -> packed ----------------
__global__ void gather_kernel(const float* __restrict__ s, const float* __restrict__ v,
                              const int* __restrict__ a2a, const float* __restrict__ invn,
                              uint2* __restrict__ sagg_p, uint2* __restrict__ vagg_p)
{
    int n = blockIdx.x;
    __shared__ int nb[KNB];
    __shared__ float invsh;
    if (threadIdx.x < KNB) nb[threadIdx.x] = a2a[n * KNB + threadIdx.x];
    if (threadIdx.x == KNB) invsh = invn[n];
    __syncthreads();
    size_t b0 = (size_t)nb[0] * HD, b1 = (size_t)nb[1] * HD, b2 = (size_t)nb[2] * HD;
    size_t b3 = (size_t)nb[3] * HD, b4 = (size_t)nb[4] * HD, b5 = (size_t)nb[5] * HD;
    for (int j = threadIdx.x; j < JP_H; j += blockDim.x) {
        float a0 = 0.f, a1 = 0.f;
        if (j < 550) {
            int h = 2 * j;
            a0 = s[b0+h] + s[b1+h] + s[b2+h] + s[b3+h] + s[b4+h] + s[b5+h];
            h++;
            a1 = s[b0+h] + s[b1+h] + s[b2+h] + s[b3+h] + s[b4+h] + s[b5+h];
        }
        sagg_p[(size_t)n * JP_H + j] = splitpack(a0, a1);
    }
    float sc = invsh;
    size_t c0 = b0*3, c1 = b1*3, c2 = b2*3, c3 = b3*3, c4 = b4*3, c5 = b5*3;
    for (int t = threadIdx.x; t < 3 * JP_H; t += blockDim.x) {
        int c = t / JP_H, j = t % JP_H;
        float a0 = 0.f, a1 = 0.f;
        if (j < 550) {
            int e = c * HD + 2 * j;
            a0 = (v[c0+e] + v[c1+e] + v[c2+e] + v[c3+e] + v[c4+e] + v[c5+e]) * sc;
            e++;
            a1 = (v[c0+e] + v[c1+e] + v[c2+e] + v[c3+e] + v[c4+e] + v[c5+e]) * sc;
        }
        vagg_p[((size_t)n * 3 + c) * JP_H + j] = splitpack(a0, a1);
    }
}

// ---------------- output-stage concat builders (gather fused) ----------------
// osin K layout: [fa(134) | sum_nb s (1100)]
__global__ void build_osin_kernel(const float* __restrict__ fa, const float* __restrict__ s,
                                  const int* __restrict__ a2a, uint2* __restrict__ osin_p)
{
    int n = blockIdx.x;
    __shared__ int nb[KNB];
    if (threadIdx.x < KNB) nb[threadIdx.x] = a2a[n * KNB + threadIdx.x];
    __syncthreads();
    size_t b0 = (size_t)nb[0] * HD, b1 = (size_t)nb[1] * HD, b2 = (size_t)nb[2] * HD;
    size_t b3 = (size_t)nb[3] * HD, b4 = (size_t)nb[4] * HD, b5 = (size_t)nb[5] * HD;
    for (int j = threadIdx.x; j < JP_OS; j += blockDim.x) {
        float v[2];
        #pragma unroll
        for (int e = 0; e < 2; e++) {
            int k = 2 * j + e;
            if (k < FD)        v[e] = fa[(size_t)n * FD + k];
            else if (k < 134)  v[e] = 0.f;
            else if (k < 1234) {
                int h = k - 134;
                v[e] = s[b0+h] + s[b1+h] + s[b2+h] + s[b3+h] + s[b4+h] + s[b5+h];
            } else v[e] = 0.f;
        }
        osin_p[(size_t)n * JP_OS + j] = splitpack(v[0], v[1]);
    }
}

// ovin K layout per row (n*3+c): [vi(1100) | sum_nb v (1100)]
__global__ void build_ovin_kernel(const float* __restrict__ vi, const float* __restrict__ v,
                                  const int* __restrict__ a2a, uint2* __restrict__ ovin_p)
{
    int n = blockIdx.x;
    __shared__ int nb[KNB];
    if (threadIdx.x < KNB) nb[threadIdx.x] = a2a[n * KNB + threadIdx.x];
    __syncthreads();
    size_t c0 = (size_t)nb[0]*3*HD, c1 = (size_t)nb[1]*3*HD, c2 = (size_t)nb[2]*3*HD;
    size_t c3 = (size_t)nb[3]*3*HD, c4 = (size_t)nb[4]*3*HD, c5 = (size_t)nb[5]*3*HD;
    for (int t = threadIdx.x; t < 3 * JP_OV; t += blockDim.x) {
        int c = t / JP_OV, j = t % JP_OV;
        float val[2];
        #pragma unroll
        for (int e = 0; e < 2; e++) {
            int k = 2 * j + e;
            if (k < HD)        val[e] = vi[((size_t)n * 3 + c) * HD + k];
            else if (k < 2200) {
                int h = c * HD + (k - HD);
                val[e] = v[c0+h] + v[c1+h] + v[c2+h] + v[c3+h] + v[c4+h] + v[c5+h];
            } else val[e] = 0.f;
        }
        ovin_p[((size_t)n * 3 + c) * JP_OV + j] = splitpack(val[0], val[1]);
    }
}

// o[n] = [osb | sum_c ovb]
__global__ void build_o_kernel(const float* __restrict__ osb, const float* __restrict__ ovb,
                               float* __restrict__ o)
{
    for (long idx = (long)blockIdx.x * blockDim.x + threadIdx.x; idx < (long)NA * FFK;
         idx += (long)gridDim.x * blockDim.x) {
        int n = (int)(idx / FFK);
        int j = (int)(idx % FFK);
        if (j < FHD) {
            o[idx] = osb[(size_t)n * FHD + j];
        } else {
            int jj = j - FHD;
            size_t b = (size_t)n * 3 * FHD + jj;
            o[idx] = ovb[b] + ovb[b + FHD] + ovb[b + 2 * FHD];
        }
    }
}

// ---------------- readout ----------------
__global__ void mol_start_kernel(const int* __restrict__ ids, int* __restrict__ start)
{
    int m = blockIdx.x * blockDim.x + threadIdx.x;
    if (m > NM) return;
    int lo = 0, hi = NA;
    while (lo < hi) {
        int mid = (lo + hi) >> 1;
        if (ids[mid] < m) lo = mid + 1; else hi = mid;
    }
    start[m] = lo;
}

__global__ void segment_mean_kernel(const float* __restrict__ o, const int* __restrict__ start,
                                    uint2* __restrict__ mol_p)
{
    int m = blockIdx.x;
    int s0 = start[m], e0 = start[m + 1];
    int cnt = e0 - s0;
    if (s0 == 0 && e0 > 0) cnt -= 1;   // atom 0 is padding
    float sc = 1.f / (float)max(cnt, 1);
    for (int t = threadIdx.x; t < JP_FF; t += blockDim.x) {
        float a0 = 0.f, a1 = 0.f;
        if (t < FHD * 2 / 2 && 2 * t < FFK) {
            int f = 2 * t;
            for (int n = s0; n < e0; n++) {
                if (n == 0) continue;
                a0 += o[(size_t)n * FFK + f];
                a1 += o[(size_t)n * FFK + f + 1];
            }
            a0 *= sc; a1 *= sc;
        }
        mol_p[(size_t)m * JP_FF + t] = splitpack(a0, a1);
    }
}

__global__ void ffn_out_kernel(const float* __restrict__ h, const float* __restrict__ W2,
                               const float* __restrict__ b2, float* __restrict__ out)
{
    int m = blockIdx.x;
    float acc = 0.f;
    for (int j = threadIdx.x; j < FHD; j += 256) acc += h[m * FHD + j] * W2[j];
    __shared__ float red[256];
    red[threadIdx.x] = acc;
    __syncthreads();
    for (int st = 128; st > 0; st >>= 1) {
        if (threadIdx.x < st) red[threadIdx.x] += red[threadIdx.x + st];
        __syncthreads();
    }
    if (threadIdx.x == 0) out[m] = red[0] + b2[0];
}

// ---------------- launch ----------------
extern "C" void kernel_launch(void* const* d_in, const int* in_sizes, int n_in,
                              void* d_out, int out_size)
{
    const float* f_atoms = (const float*)d_in[0];
    const float* f_bonds = (const float*)d_in[1];
    const float* W_is    = (const float*)d_in[2];
    const float* W_iv    = (const float*)d_in[3];
    const float* W_hs    = (const float*)d_in[4];
    const float* W_hv    = (const float*)d_in[5];
    const float* W_os    = (const float*)d_in[6];
    const float* b_os    = (const float*)d_in[7];
    const float* W_ov    = (const float*)d_in[8];
    const float* b_ov    = (const float*)d_in[9];
    const float* ffn_W1  = (const float*)d_in[10];
    const float* ffn_b1  = (const float*)d_in[11];
    const float* ffn_W2  = (const float*)d_in[12];
    const float* ffn_b2  = (const float*)d_in[13];
    const int*   a2a     = (const int*)d_in[14];
    const int*   a2b     = (const int*)d_in[15];
    const int*   mol_ids = (const int*)d_in[16];
    float*       out     = (float*)d_out;

    uint2 *p_fa, *p_X, *p_sagg, *p_vagg, *p_osin, *p_ovin, *p_mol;
    uint2 *p_Wis, *p_Wiv, *p_Whs, *p_Whv, *p_Wos, *p_Wov, *p_Wff;
    float *p_si, *p_s, *p_vi, *p_v, *p_osb, *p_ovb, *p_o, *p_h, *p_invn;
    int* p_molstart;
    cudaGetSymbolAddress((void**)&p_fa,   g_fa_p);
    cudaGetSymbolAddress((void**)&p_X,    g_X_p);
    cudaGetSymbolAddress((void**)&p_sagg, g_sagg_p);
    cudaGetSymbolAddress((void**)&p_vagg, g_vagg_p);
    cudaGetSymbolAddress((void**)&p_osin, g_osin_p);
    cudaGetSymbolAddress((void**)&p_ovin, g_ovin_p);
    cudaGetSymbolAddress((void**)&p_mol,  g_mol_p);
    cudaGetSymbolAddress((void**)&p_Wis,  g_Wis_p);
    cudaGetSymbolAddress((void**)&p_Wiv,  g_Wiv_p);
    cudaGetSymbolAddress((void**)&p_Whs,  g_Whs_p);
    cudaGetSymbolAddress((void**)&p_Whv,  g_Whv_p);
    cudaGetSymbolAddress((void**)&p_Wos,  g_Wos_p);
    cudaGetSymbolAddress((void**)&p_Wov,  g_Wov_p);
    cudaGetSymbolAddress((void**)&p_Wff,  g_Wff_p);
    cudaGetSymbolAddress((void**)&p_si,   g_si);
    cudaGetSymbolAddress((void**)&p_s,    g_s);
    cudaGetSymbolAddress((void**)&p_vi,   g_vi);
    cudaGetSymbolAddress((void**)&p_v,    g_v);
    cudaGetSymbolAddress((void**)&p_osb,  g_osb);
    cudaGetSymbolAddress((void**)&p_ovb,  g_ovb);
    cudaGetSymbolAddress((void**)&p_o,    g_o);
    cudaGetSymbolAddress((void**)&p_h,    g_h);
    cudaGetSymbolAddress((void**)&p_invn, g_invn);
    cudaGetSymbolAddress((void**)&p_molstart, g_molstart);

    // 0. weight packing (graph-capturable, deterministic)
    packW_kernel<<<512, 256>>>(W_is, HD, JP_FA, 0, 133, 0, 0, 0, 0, p_Wis);
    packW_kernel<<<512, 256>>>(W_iv, HD, JP_X, 0, 133, 0, 133, 133, 134, p_Wiv);
    packW_kernel<<<1024, 256>>>(W_hs, HD, JP_H, 0, 1100, 0, 0, 0, 0, p_Whs);
    packW_kernel<<<1024, 256>>>(W_hv, HD, JP_H, 0, 1100, 0, 0, 0, 0, p_Whv);
    packW_kernel<<<1024, 256>>>(W_os, FHD, JP_OS, 0, 133, 0, 133, 1100, 134, p_Wos);
    packW_kernel<<<1024, 256>>>(W_ov, FHD, JP_OV, 0, 2200, 0, 0, 0, 0, p_Wov);
    packW_kernel<<<1024, 256>>>(ffn_W1, FHD, JP_FF, 0, 1400, 0, 0, 0, 0, p_Wff);

    // 1. prep
    invnorm_kernel<<<(NA + 255) / 256, 256>>>(a2a, p_invn);
    pack_fa_kernel<<<2048, 256>>>(f_atoms, p_fa);
    build_X_kernel<<<NA, 192>>>(f_atoms, f_bonds, a2a, a2b, p_X);

    // 2. si = f_atoms @ W_is
    dim3 gsi((HD + BN - 1) / BN, (NA + BM - 1) / BM);
    bgemm_kernel<true, false, false, true><<<gsi, 256>>>(
        p_fa, p_Wis, nullptr, nullptr, p_s, p_si, NA, HD, 9, JP_FA);

    // 3. vi = X @ W_iv
    dim3 gvi((HD + BN - 1) / BN, (3 * NA + BM - 1) / BM);
    bgemm_kernel<true, false, false, true><<<gvi, 256>>>(
        p_X, p_Wiv, nullptr, nullptr, p_v, p_vi, 3 * NA, HD, 17, JP_X);

    // 4. message passing
    for (int it = 0; it < 6; it++) {
        gather_kernel<<<NA, 256>>>(p_s, p_v, a2a, p_invn, p_sagg, p_vagg);
        bgemm_kernel<true, true, false, false><<<gsi, 256>>>(
            p_sagg, p_Whs, p_si, nullptr, p_s, nullptr, NA, HD, 69, JP_H);
        bgemm_kernel<true, true, false, false><<<gvi, 256>>>(
            p_vagg, p_Whv, p_vi, nullptr, p_v, nullptr, 3 * NA, HD, 69, JP_H);
    }

    // 5. output stage (gathers fused into concat builders)
    build_osin_kernel<<<NA, 256>>>(f_atoms, p_s, a2a, p_osin);
    build_ovin_kernel<<<NA, 256>>>(p_vi, p_v, a2a, p_ovin);
    dim3 gos((FHD + BN - 1) / BN, (NA + BM - 1) / BM);
    bgemm_kernel<true, false, true, false><<<gos, 256>>>(
        p_osin, p_Wos, nullptr, b_os, p_osb, nullptr, NA, FHD, 78, JP_OS);
    dim3 gov((FHD + BN - 1) / BN, (3 * NA + BM - 1) / BM);
    bgemm_kernel<true, false, true, false><<<gov, 256>>>(
        p_ovin, p_Wov, nullptr, b_ov, p_ovb, nullptr, 3 * NA, FHD, 138, JP_OV);
    {
        long tot3 = (long)NA * FFK;
        build_o_kernel<<<(unsigned)((tot3 + 255) / 256), 256>>>(p_osb, p_ovb, p_o);
    }

    // 6. readout + FFN
    mol_start_kernel<<<4, 256>>>(mol_ids, p_molstart);
    segment_mean_kernel<<<NM, 256>>>(p_o, p_molstart, p_mol);
    dim3 gff((FHD + BN - 1) / BN, (NM + BM - 1) / BM);
    bgemm_kernel<true, false, true, false><<<gff, 256>>>(
        p_mol, p_Wff, nullptr, ffn_b1, p_h, nullptr, NM, FHD, 88, JP_FF);
    ffn_out_kernel<<<NM, 256>>>(p_h, ffn_W2, ffn_b2, out);
}

// round 8
// speedup vs baseline: 2.6135x; 1.0699x over previous
#include <cuda_runtime.h>
#include <cstdint>

// ---------------- Problem constants ----------------
#define NA   20001
#define FD   133
#define KNB  6
#define HD   1100
#define FHD  700
#define NM   800
#define FFK  1400

// K paddings in PAIRS (bf16x2). Multiples of 16 pairs = 32 elems (one stage).
#define JP_FA   80      // si : T=5
#define JP_X    144     // vi : T=9
#define JP_H    560     // hs/hv : T=35
#define JP_OS   624     // os : T=39
#define JP_OV   1104    // ov : T=69
#define JP_FF   704     // ffn : T=44

// ---------------- Scratch (device globals) ----------------
__device__ __align__(16) uint2 g_fa_p  [(size_t)NA * JP_FA];
__device__ __align__(16) uint2 g_X_p   [(size_t)NA * 3 * JP_X];
__device__ __align__(16) uint2 g_sagg_p[(size_t)NA * JP_H];
__device__ __align__(16) uint2 g_vagg_p[(size_t)NA * 3 * JP_H];
__device__ __align__(16) uint2 g_osin_p[(size_t)NA * JP_OS];
__device__ __align__(16) uint2 g_ovin_p[(size_t)NA * 3 * JP_OV];
__device__ __align__(16) uint2 g_mol_p [(size_t)NM * JP_FF];

__device__ __align__(16) uint2 g_Wis_p [(size_t)JP_FA * HD];
__device__ __align__(16) uint2 g_Wiv_p [(size_t)JP_X  * HD];
__device__ __align__(16) uint2 g_Whs_p [(size_t)JP_H  * HD];
__device__ __align__(16) uint2 g_Whv_p [(size_t)JP_H  * HD];
__device__ __align__(16) uint2 g_Wos_p [(size_t)JP_OS * FHD];
__device__ __align__(16) uint2 g_Wov_p [(size_t)JP_OV * FHD];
__device__ __align__(16) uint2 g_Wff_p [(size_t)JP_FF * FHD];

__device__ __align__(16) float g_si [(size_t)NA * HD];
__device__ __align__(16) float g_s  [(size_t)NA * HD];
__device__ __align__(16) float g_vi [(size_t)NA * 3 * HD];
__device__ __align__(16) float g_v  [(size_t)NA * 3 * HD];
__device__ __align__(16) float g_osb[(size_t)NA * FHD];
__device__ __align__(16) float g_ovb[(size_t)NA * 3 * FHD];
__device__ __align__(16) float g_o  [(size_t)NA * FFK];
__device__ __align__(16) float g_h  [NM * FHD];
__device__ __align__(16) float g_invn[NA];
__device__ int g_molstart[NM + 1];

// ---------------- bf16 split-pack helper ----------------
__device__ __forceinline__ uint2 splitpack(float x0, float x1) {
    unsigned h;
    asm("cvt.rn.bf16x2.f32 %0, %1, %2;" : "=r"(h) : "f"(x1), "f"(x0));
    float h0 = __uint_as_float(h << 16);
    float h1 = __uint_as_float(h & 0xFFFF0000u);
    unsigned l;
    asm("cvt.rn.bf16x2.f32 %0, %1, %2;" : "=r"(l) : "f"(x1 - h1), "f"(x0 - h0));
    return make_uint2(h, l);
}

__device__ __forceinline__ void cp16(void* dst_smem, const void* src, int bytes) {
    unsigned sa = (unsigned)__cvta_generic_to_shared(dst_smem);
    asm volatile("cp.async.ca.shared.global [%0], [%1], 16, %2;\n"
                 :: "r"(sa), "l"(src), "r"(bytes));
}

#define MMA_BF16(ACC, AF, BF)                                                   \
    asm volatile(                                                               \
        "mma.sync.aligned.m16n8k16.row.col.f32.bf16.bf16.f32 "                  \
        "{%0,%1,%2,%3}, {%4,%5,%6,%7}, {%8,%9}, {%0,%1,%2,%3};\n"               \
        : "+f"(ACC[0]), "+f"(ACC[1]), "+f"(ACC[2]), "+f"(ACC[3])                \
        : "r"(AF[0]), "r"(AF[1]), "r"(AF[2]), "r"(AF[3]),                       \
          "r"(BF[0]), "r"(BF[1]))

// ---------------- bf16x3 GEMM, BK=32 elems/stage, double-buffered ----------------
// A_p[m][j] pairs; B_p[j][n] pairs; C = act(A@B [+Add] [+bias]).
// smem stage: A 128 rows x 16 pairs (stride 18), B 16 pair-rows x 128 (stride 132).
#define ASTP 18
#define BSTP 132
#define STG_A (128 * ASTP)            // uint2
#define STG_B (16 * BSTP)             // uint2
#define STG_U2 (STG_A + STG_B)        // 4416 uint2 = 35328 B
#define SMEM_GEMM (2 * STG_U2 * 8)    // 70656 B

template<bool RELU, bool HAS_ADD, bool HAS_BIAS, bool WRITE_RAW>
__global__ __launch_bounds__(256, 2)
void bgemm_kernel(const uint2* __restrict__ A, const uint2* __restrict__ B,
                  const float* __restrict__ Add, const float* __restrict__ bias,
                  float* __restrict__ C, float* __restrict__ Craw,
                  int M, int N, int T, int ldp)
{
    extern __shared__ __align__(16) uint2 smem_u2[];

    const int tid = threadIdx.x;
    const int rowBase = blockIdx.y * 128;
    const int colBase = blockIdx.x * 128;
    const int warpId = tid >> 5;
    const int lane = tid & 31;
    const int g  = lane >> 2;
    const int tg = lane & 3;
    const int wm = (warpId & 1) * 64;
    const int wn = (warpId >> 1) * 32;

    float acc[4][4][4];
    #pragma unroll
    for (int mi = 0; mi < 4; mi++)
        #pragma unroll
        for (int ni = 0; ni < 4; ni++)
            #pragma unroll
            for (int j = 0; j < 4; j++) acc[mi][ni][j] = 0.f;

    auto load_stage = [&](int t, int st) {
        uint2* As = smem_u2 + st * STG_U2;
        uint2* Bs = As + STG_A;
        #pragma unroll
        for (int i = 0; i < 4; i++) {        // A: 1024 chunks (16B = 2 pairs)
            int c = tid + i * 256;
            int m = c >> 3, q = c & 7;
            int gm = rowBase + m;
            bool ok = gm < M;
            const uint2* src = ok ? (A + (size_t)gm * ldp + t * 16 + q * 2) : A;
            cp16(&As[m * ASTP + q * 2], src, ok ? 16 : 0);
        }
        #pragma unroll
        for (int i = 0; i < 4; i++) {        // B: 1024 chunks (2 cols)
            int c = tid + i * 256;
            int j = c >> 6, q = c & 63;
            int gn = colBase + q * 2;
            bool ok = gn < N;
            const uint2* src = ok ? (B + (size_t)(t * 16 + j) * N + gn) : B;
            cp16(&Bs[j * BSTP + q * 2], src, ok ? 16 : 0);
        }
        asm volatile("cp.async.commit_group;\n");
    };

    load_stage(0, 0);

    for (int t = 0; t < T; t++) {
        const int st = t & 1;
        if (t + 1 < T) {
            load_stage(t + 1, st ^ 1);
            asm volatile("cp.async.wait_group 1;\n");
        } else {
            asm volatile("cp.async.wait_group 0;\n");
        }
        __syncthreads();

        const uint2* As = smem_u2 + st * STG_U2;
        const uint2* Bs = As + STG_A;

        #pragma unroll
        for (int ks = 0; ks < 2; ks++) {
            const int kb = ks * 8;
            unsigned ah[4][4], al[4][4], bh[4][2], bl[4][2];
            #pragma unroll
            for (int mi = 0; mi < 4; mi++) {
                int r = wm + mi * 16 + g;
                uint2 p0 = As[r * ASTP + kb + tg];
                uint2 p1 = As[(r + 8) * ASTP + kb + tg];
                uint2 p2 = As[r * ASTP + kb + 4 + tg];
                uint2 p3 = As[(r + 8) * ASTP + kb + 4 + tg];
                ah[mi][0] = p0.x; ah[mi][1] = p1.x; ah[mi][2] = p2.x; ah[mi][3] = p3.x;
                al[mi][0] = p0.y; al[mi][1] = p1.y; al[mi][2] = p2.y; al[mi][3] = p3.y;
            }
            #pragma unroll
            for (int ni = 0; ni < 4; ni++) {
                int n = wn + ni * 8 + g;
                uint2 q0 = Bs[(kb + tg) * BSTP + n];
                uint2 q1 = Bs[(kb + 4 + tg) * BSTP + n];
                bh[ni][0] = q0.x; bh[ni][1] = q1.x;
                bl[ni][0] = q0.y; bl[ni][1] = q1.y;
            }
            #pragma unroll
            for (int mi = 0; mi < 4; mi++)
                #pragma unroll
                for (int ni = 0; ni < 4; ni++) {
                    MMA_BF16(acc[mi][ni], ah[mi], bl[ni]);   // hi*lo
                    MMA_BF16(acc[mi][ni], al[mi], bh[ni]);   // lo*hi
                    MMA_BF16(acc[mi][ni], ah[mi], bh[ni]);   // hi*hi last
                }
        }
        __syncthreads();
    }

    #pragma unroll
    for (int mi = 0; mi < 4; mi++) {
        int r0 = rowBase + wm + mi * 16 + g;
        #pragma unroll
        for (int ni = 0; ni < 4; ni++) {
            int cN = colBase + wn + ni * 8 + tg * 2;
            if (cN >= N) continue;
            #pragma unroll
            for (int half = 0; half < 2; half++) {
                int r = r0 + half * 8;
                if (r >= M) continue;
                size_t idx = (size_t)r * N + cN;
                float2 vv;
                vv.x = acc[mi][ni][half * 2 + 0];
                vv.y = acc[mi][ni][half * 2 + 1];
                if (HAS_ADD) {
                    float2 a = *(const float2*)(Add + idx);
                    vv.x += a.x; vv.y += a.y;
                }
                if (HAS_BIAS) {
                    float2 b = *(const float2*)(bias + cN);
                    vv.x += b.x; vv.y += b.y;
                }
                if (WRITE_RAW) *(float2*)(Craw + idx) = vv;
                if (RELU) { vv.x = fmaxf(vv.x, 0.f); vv.y = fmaxf(vv.y, 0.f); }
                *(float2*)(C + idx) = vv;
            }
        }
    }
}

// ---------------- weight split-pack (2-segment k remap), layout [j][n] ----------------
__global__ void packW_kernel(const float* __restrict__ W, int N, int Jtot,
                             int s0, int l0, int d0, int s1, int l1, int d1,
                             uint2* __restrict__ out)
{
    long tot = (long)Jtot * N;
    for (long idx = (long)blockIdx.x * blockDim.x + threadIdx.x; idx < tot;
         idx += (long)gridDim.x * blockDim.x) {
        int j = (int)(idx / N), n = (int)(idx % N);
        float v[2];
        #pragma unroll
        for (int e = 0; e < 2; e++) {
            int k = 2 * j + e, row = -1;
            if (k >= d1 && k < d1 + l1) row = s1 + (k - d1);
            else if (k >= d0 && k < d0 + l0) row = s0 + (k - d0);
            v[e] = (row < 0) ? 0.f : W[(size_t)row * N + n];
        }
        out[idx] = splitpack(v[0], v[1]);
    }
}

// ---------------- invnorm ----------------
__global__ void invnorm_kernel(const int* __restrict__ a2a, float* __restrict__ invn)
{
    int n = blockIdx.x * blockDim.x + threadIdx.x;
    if (n >= NA) return;
    int cnt = 0;
    #pragma unroll
    for (int k = 0; k < KNB; k++) cnt += (a2a[n * KNB + k] > 0) ? 1 : 0;
    invn[n] = 1.f / (float)max(cnt, 1);
}

// ---------------- f_atoms -> packed ----------------
__global__ void pack_fa_kernel(const float* __restrict__ fa, uint2* __restrict__ out)
{
    long tot = (long)NA * JP_FA;
    for (long idx = (long)blockIdx.x * blockDim.x + threadIdx.x; idx < tot;
         idx += (long)gridDim.x * blockDim.x) {
        int n = (int)(idx / JP_FA), j = (int)(idx % JP_FA);
        int k0 = 2 * j;
        float v0 = (k0     < FD) ? fa[(size_t)n * FD + k0]     : 0.f;
        float v1 = (k0 + 1 < FD) ? fa[(size_t)n * FD + k0 + 1] : 0.f;
        out[idx] = splitpack(v0, v1);
    }
}

// ---------------- build X packed: rows (n*3+c), K layout [a(134)|self(134)] ----------------
__global__ void build_X_kernel(const float* __restrict__ f_atoms, const float* __restrict__ f_bonds,
                               const int* __restrict__ a2a, const int* __restrict__ a2b,
                               uint2* __restrict__ Xp)
{
    int n = blockIdx.x;
    __shared__ int   nb[KNB];
    __shared__ float bond[KNB][3];
    __shared__ float stg[6][134];
    if (threadIdx.x < KNB) {
        int k = threadIdx.x;
        nb[k] = a2a[n * KNB + k];
        int b = a2b[n * KNB + k];
        bond[k][0] = f_bonds[(size_t)b * 3 + 0];
        bond[k][1] = f_bonds[(size_t)b * 3 + 1];
        bond[k][2] = f_bonds[(size_t)b * 3 + 2];
    }
    if (threadIdx.x < 6) stg[threadIdx.x][133] = 0.f;
    __syncthreads();
    float ms0 = 0.f, ms1 = 0.f, ms2 = 0.f;
    #pragma unroll
    for (int k = 0; k < KNB; k++) {
        float mk = (nb[k] > 0) ? 1.f : 0.f;
        ms0 += mk * bond[k][0];
        ms1 += mk * bond[k][1];
        ms2 += mk * bond[k][2];
    }
    for (int f = threadIdx.x; f < FD; f += blockDim.x) {
        float selfv = f_atoms[(size_t)n * FD + f];
        float a0 = 0.f, a1 = 0.f, a2 = 0.f;
        #pragma unroll
        for (int k = 0; k < KNB; k++) {
            float fv = f_atoms[(size_t)nb[k] * FD + f];
            a0 += fv * bond[k][0];
            a1 += fv * bond[k][1];
            a2 += fv * bond[k][2];
        }
        stg[0][f] = a0; stg[1][f] = a1; stg[2][f] = a2;
        stg[3][f] = selfv * ms0; stg[4][f] = selfv * ms1; stg[5][f] = selfv * ms2;
    }
    __syncthreads();
    for (int t = threadIdx.x; t < 3 * JP_X; t += blockDim.x) {
        int c = t / JP_X, j = t % JP_X;
        float v[2];
        #pragma unroll
        for (int e = 0; e < 2; e++) {
            int k = 2 * j + e;
            if (k < 134)      v[e] = stg[c][k];
            else if (k < 268) v[e] = stg[3 + c][k - 134];
            else              v[e] = 0.f;
        }
        Xp[((size_t)n * 3 + c) * JP_X + j] = splitpack(v[0], v[1]);
    }
}

// ---------------- message-passing gather -> packed ----------------
__global__ void gather_kernel(const float* __restrict__ s, const float* __restrict__ v,
                              const int* __restrict__ a2a, const float* __restrict__ invn,
                              uint2* __restrict__ sagg_p, uint2* __restrict__ vagg_p)
{
    int n = blockIdx.x;
    __shared__ int nb[KNB];
    __shared__ float invsh;
    if (threadIdx.x < KNB) nb[threadIdx.x] = a2a[n * KNB + threadIdx.x];
    if (threadIdx.x == KNB) invsh = invn[n];
    __syncthreads();
    size_t b0 = (size_t)nb[0] * HD, b1 = (size_t)nb[1] * HD, b2 = (size_t)nb[2] * HD;
    size_t b3 = (size_t)nb[3] * HD, b4 = (size_t)nb[4] * HD, b5 = (size_t)nb[5] * HD;
    for (int j = threadIdx.x; j < JP_H; j += blockDim.x) {
        float a0 = 0.f, a1 = 0.f;
        if (j < 550) {
            int h = 2 * j;
            a0 = s[b0+h] + s[b1+h] + s[b2+h] + s[b3+h] + s[b4+h] + s[b5+h];
            h++;
            a1 = s[b0+h] + s[b1+h] + s[b2+h] + s[b3+h] + s[b4+h] + s[b5+h];
        }
        sagg_p[(size_t)n * JP_H + j] = splitpack(a0, a1);
    }
    float sc = invsh;
    size_t c0 = b0*3, c1 = b1*3, c2 = b2*3, c3 = b3*3, c4 = b4*3, c5 = b5*3;
    for (int t = threadIdx.x; t < 3 * JP_H; t += blockDim.x) {
        int c = t / JP_H, j = t % JP_H;
        float a0 = 0.f, a1 = 0.f;
        if (j < 550) {
            int e = c * HD + 2 * j;
            a0 = (v[c0+e] + v[c1+e] + v[c2+e] + v[c3+e] + v[c4+e] + v[c5+e]) * sc;
            e++;
            a1 = (v[c0+e] + v[c1+e] + v[c2+e] + v[c3+e] + v[c4+e] + v[c5+e]) * sc;
        }
        vagg_p[((size_t)n * 3 + c) * JP_H + j] = splitpack(a0, a1);
    }
}

// ---------------- output-stage concat builders (gather fused) ----------------
__global__ void build_osin_kernel(const float* __restrict__ fa, const float* __restrict__ s,
                                  const int* __restrict__ a2a, uint2* __restrict__ osin_p)
{
    int n = blockIdx.x;
    __shared__ int nb[KNB];
    if (threadIdx.x < KNB) nb[threadIdx.x] = a2a[n * KNB + threadIdx.x];
    __syncthreads();
    size_t b0 = (size_t)nb[0] * HD, b1 = (size_t)nb[1] * HD, b2 = (size_t)nb[2] * HD;
    size_t b3 = (size_t)nb[3] * HD, b4 = (size_t)nb[4] * HD, b5 = (size_t)nb[5] * HD;
    for (int j = threadIdx.x; j < JP_OS; j += blockDim.x) {
        float v[2];
        #pragma unroll
        for (int e = 0; e < 2; e++) {
            int k = 2 * j + e;
            if (k < FD)        v[e] = fa[(size_t)n * FD + k];
            else if (k < 134)  v[e] = 0.f;
            else if (k < 1234) {
                int h = k - 134;
                v[e] = s[b0+h] + s[b1+h] + s[b2+h] + s[b3+h] + s[b4+h] + s[b5+h];
            } else v[e] = 0.f;
        }
        osin_p[(size_t)n * JP_OS + j] = splitpack(v[0], v[1]);
    }
}

__global__ void build_ovin_kernel(const float* __restrict__ vi, const float* __restrict__ v,
                                  const int* __restrict__ a2a, uint2* __restrict__ ovin_p)
{
    int n = blockIdx.x;
    __shared__ int nb[KNB];
    if (threadIdx.x < KNB) nb[threadIdx.x] = a2a[n * KNB + threadIdx.x];
    __syncthreads();
    size_t c0 = (size_t)nb[0]*3*HD, c1 = (size_t)nb[1]*3*HD, c2 = (size_t)nb[2]*3*HD;
    size_t c3 = (size_t)nb[3]*3*HD, c4 = (size_t)nb[4]*3*HD, c5 = (size_t)nb[5]*3*HD;
    for (int t = threadIdx.x; t < 3 * JP_OV; t += blockDim.x) {
        int c = t / JP_OV, j = t % JP_OV;
        float val[2];
        #pragma unroll
        for (int e = 0; e < 2; e++) {
            int k = 2 * j + e;
            if (k < HD)        val[e] = vi[((size_t)n * 3 + c) * HD + k];
            else if (k < 2200) {
                int h = c * HD + (k - HD);
                val[e] = v[c0+h] + v[c1+h] + v[c2+h] + v[c3+h] + v[c4+h] + v[c5+h];
            } else val[e] = 0.f;
        }
        ovin_p[((size_t)n * 3 + c) * JP_OV + j] = splitpack(val[0], val[1]);
    }
}

// o[n] = [osb | sum_c ovb]
__global__ void build_o_kernel(const float* __restrict__ osb, const float* __restrict__ ovb,
                               float* __restrict__ o)
{
    for (long idx = (long)blockIdx.x * blockDim.x + threadIdx.x; idx < (long)NA * FFK;
         idx += (long)gridDim.x * blockDim.x) {
        int n = (int)(idx / FFK);
        int j = (int)(idx % FFK);
        if (j < FHD) {
            o[idx] = osb[(size_t)n * FHD + j];
        } else {
            int jj = j - FHD;
            size_t b = (size_t)n * 3 * FHD + jj;
            o[idx] = ovb[b] + ovb[b + FHD] + ovb[b + 2 * FHD];
        }
    }
}

// ---------------- readout ----------------
__global__ void mol_start_kernel(const int* __restrict__ ids, int* __restrict__ start)
{
    int m = blockIdx.x * blockDim.x + threadIdx.x;
    if (m > NM) return;
    int lo = 0, hi = NA;
    while (lo < hi) {
        int mid = (lo + hi) >> 1;
        if (ids[mid] < m) lo = mid + 1; else hi = mid;
    }
    start[m] = lo;
}

__global__ void segment_mean_kernel(const float* __restrict__ o, const int* __restrict__ start,
                                    uint2* __restrict__ mol_p)
{
    int m = blockIdx.x;
    int s0 = start[m], e0 = start[m + 1];
    int cnt = e0 - s0;
    if (s0 == 0 && e0 > 0) cnt -= 1;   // atom 0 is padding
    float sc = 1.f / (float)max(cnt, 1);
    for (int t = threadIdx.x; t < JP_FF; t += blockDim.x) {
        float a0 = 0.f, a1 = 0.f;
        int f = 2 * t;
        if (f < FFK) {
            for (int n = s0; n < e0; n++) {
                if (n == 0) continue;
                a0 += o[(size_t)n * FFK + f];
                a1 += o[(size_t)n * FFK + f + 1];
            }
            a0 *= sc; a1 *= sc;
        }
        mol_p[(size_t)m * JP_FF + t] = splitpack(a0, a1);
    }
}

__global__ void ffn_out_kernel(const float* __restrict__ h, const float* __restrict__ W2,
                               const float* __restrict__ b2, float* __restrict__ out)
{
    int m = blockIdx.x;
    float acc = 0.f;
    for (int j = threadIdx.x; j < FHD; j += 256) acc += h[m * FHD + j] * W2[j];
    __shared__ float red[256];
    red[threadIdx.x] = acc;
    __syncthreads();
    for (int st = 128; st > 0; st >>= 1) {
        if (threadIdx.x < st) red[threadIdx.x] += red[threadIdx.x + st];
        __syncthreads();
    }
    if (threadIdx.x == 0) out[m] = red[0] + b2[0];
}

// ---------------- launch ----------------
extern "C" void kernel_launch(void* const* d_in, const int* in_sizes, int n_in,
                              void* d_out, int out_size)
{
    const float* f_atoms = (const float*)d_in[0];
    const float* f_bonds = (const float*)d_in[1];
    const float* W_is    = (const float*)d_in[2];
    const float* W_iv    = (const float*)d_in[3];
    const float* W_hs    = (const float*)d_in[4];
    const float* W_hv    = (const float*)d_in[5];
    const float* W_os    = (const float*)d_in[6];
    const float* b_os    = (const float*)d_in[7];
    const float* W_ov    = (const float*)d_in[8];
    const float* b_ov    = (const float*)d_in[9];
    const float* ffn_W1  = (const float*)d_in[10];
    const float* ffn_b1  = (const float*)d_in[11];
    const float* ffn_W2  = (const float*)d_in[12];
    const float* ffn_b2  = (const float*)d_in[13];
    const int*   a2a     = (const int*)d_in[14];
    const int*   a2b     = (const int*)d_in[15];
    const int*   mol_ids = (const int*)d_in[16];
    float*       out     = (float*)d_out;

    uint2 *p_fa, *p_X, *p_sagg, *p_vagg, *p_osin, *p_ovin, *p_mol;
    uint2 *p_Wis, *p_Wiv, *p_Whs, *p_Whv, *p_Wos, *p_Wov, *p_Wff;
    float *p_si, *p_s, *p_vi, *p_v, *p_osb, *p_ovb, *p_o, *p_h, *p_invn;
    int* p_molstart;
    cudaGetSymbolAddress((void**)&p_fa,   g_fa_p);
    cudaGetSymbolAddress((void**)&p_X,    g_X_p);
    cudaGetSymbolAddress((void**)&p_sagg, g_sagg_p);
    cudaGetSymbolAddress((void**)&p_vagg, g_vagg_p);
    cudaGetSymbolAddress((void**)&p_osin, g_osin_p);
    cudaGetSymbolAddress((void**)&p_ovin, g_ovin_p);
    cudaGetSymbolAddress((void**)&p_mol,  g_mol_p);
    cudaGetSymbolAddress((void**)&p_Wis,  g_Wis_p);
    cudaGetSymbolAddress((void**)&p_Wiv,  g_Wiv_p);
    cudaGetSymbolAddress((void**)&p_Whs,  g_Whs_p);
    cudaGetSymbolAddress((void**)&p_Whv,  g_Whv_p);
    cudaGetSymbolAddress((void**)&p_Wos,  g_Wos_p);
    cudaGetSymbolAddress((void**)&p_Wov,  g_Wov_p);
    cudaGetSymbolAddress((void**)&p_Wff,  g_Wff_p);
    cudaGetSymbolAddress((void**)&p_si,   g_si);
    cudaGetSymbolAddress((void**)&p_s,    g_s);
    cudaGetSymbolAddress((void**)&p_vi,   g_vi);
    cudaGetSymbolAddress((void**)&p_v,    g_v);
    cudaGetSymbolAddress((void**)&p_osb,  g_osb);
    cudaGetSymbolAddress((void**)&p_ovb,  g_ovb);
    cudaGetSymbolAddress((void**)&p_o,    g_o);
    cudaGetSymbolAddress((void**)&p_h,    g_h);
    cudaGetSymbolAddress((void**)&p_invn, g_invn);
    cudaGetSymbolAddress((void**)&p_molstart, g_molstart);

    cudaFuncSetAttribute(bgemm_kernel<true,false,false,true>,
                         cudaFuncAttributeMaxDynamicSharedMemorySize, SMEM_GEMM);
    cudaFuncSetAttribute(bgemm_kernel<true,true,false,false>,
                         cudaFuncAttributeMaxDynamicSharedMemorySize, SMEM_GEMM);
    cudaFuncSetAttribute(bgemm_kernel<true,false,true,false>,
                         cudaFuncAttributeMaxDynamicSharedMemorySize, SMEM_GEMM);

    // 0. weight packing
    packW_kernel<<<512, 256>>>(W_is, HD, JP_FA, 0, 133, 0, 0, 0, 0, p_Wis);
    packW_kernel<<<512, 256>>>(W_iv, HD, JP_X, 0, 133, 0, 133, 133, 134, p_Wiv);
    packW_kernel<<<1024, 256>>>(W_hs, HD, JP_H, 0, 1100, 0, 0, 0, 0, p_Whs);
    packW_kernel<<<1024, 256>>>(W_hv, HD, JP_H, 0, 1100, 0, 0, 0, 0, p_Whv);
    packW_kernel<<<1024, 256>>>(W_os, FHD, JP_OS, 0, 133, 0, 133, 1100, 134, p_Wos);
    packW_kernel<<<1024, 256>>>(W_ov, FHD, JP_OV, 0, 2200, 0, 0, 0, 0, p_Wov);
    packW_kernel<<<1024, 256>>>(ffn_W1, FHD, JP_FF, 0, 1400, 0, 0, 0, 0, p_Wff);

    // 1. prep
    invnorm_kernel<<<(NA + 255) / 256, 256>>>(a2a, p_invn);
    pack_fa_kernel<<<2048, 256>>>(f_atoms, p_fa);
    build_X_kernel<<<NA, 192>>>(f_atoms, f_bonds, a2a, a2b, p_X);

    // 2. si = f_atoms @ W_is
    dim3 gsi((HD + 127) / 128, (NA + 127) / 128);
    bgemm_kernel<true, false, false, true><<<gsi, 256, SMEM_GEMM>>>(
        p_fa, p_Wis, nullptr, nullptr, p_s, p_si, NA, HD, 5, JP_FA);

    // 3. vi = X @ W_iv
    dim3 gvi((HD + 127) / 128, (3 * NA + 127) / 128);
    bgemm_kernel<true, false, false, true><<<gvi, 256, SMEM_GEMM>>>(
        p_X, p_Wiv, nullptr, nullptr, p_v, p_vi, 3 * NA, HD, 9, JP_X);

    // 4. message passing
    for (int it = 0; it < 6; it++) {
        gather_kernel<<<NA, 256>>>(p_s, p_v, a2a, p_invn, p_sagg, p_vagg);
        bgemm_kernel<true, true, false, false><<<gsi, 256, SMEM_GEMM>>>(
            p_sagg, p_Whs, p_si, nullptr, p_s, nullptr, NA, HD, 35, JP_H);
        bgemm_kernel<true, true, false, false><<<gvi, 256, SMEM_GEMM>>>(
            p_vagg, p_Whv, p_vi, nullptr, p_v, nullptr, 3 * NA, HD, 35, JP_H);
    }

    // 5. output stage (gathers fused into concat builders)
    build_osin_kernel<<<NA, 256>>>(f_atoms, p_s, a2a, p_osin);
    build_ovin_kernel<<<NA, 256>>>(p_vi, p_v, a2a, p_ovin);
    dim3 gos((FHD + 127) / 128, (NA + 127) / 128);
    bgemm_kernel<true, false, true, false><<<gos, 256, SMEM_GEMM>>>(
        p_osin, p_Wos, nullptr, b_os, p_osb, nullptr, NA, FHD, 39, JP_OS);
    dim3 gov((FHD + 127) / 128, (3 * NA + 127) / 128);
    bgemm_kernel<true, false, true, false><<<gov, 256, SMEM_GEMM>>>(
        p_ovin, p_Wov, nullptr, b_ov, p_ovb, nullptr, 3 * NA, FHD, 69, JP_OV);
    {
        long tot3 = (long)NA * FFK;
        build_o_kernel<<<(unsigned)((tot3 + 255) / 256), 256>>>(p_osb, p_ovb, p_o);
    }

    // 6. readout + FFN
    mol_start_kernel<<<4, 256>>>(mol_ids, p_molstart);
    segment_mean_kernel<<<NM, 256>>>(p_o, p_molstart, p_mol);
    dim3 gff((FHD + 127) / 128, (NM + 127) / 128);
    bgemm_kernel<true, false, true, false><<<gff, 256, SMEM_GEMM>>>(
        p_mol, p_Wff, nullptr, ffn_b1, p_h, nullptr, NM, FHD, 44, JP_FF);
    ffn_out_kernel<<<NM, 256>>>(p_h, ffn_W2, ffn_b2, out);
}